// round 15
// baseline (speedup 1.0000x reference)
#include <cuda_runtime.h>
#include <cuda_fp16.h>
#include <cuda_bf16.h>
#include <stdint.h>
#include <cstdint>
#include <math.h>
#include <float.h>

typedef unsigned int u32;

#define S_   1024
#define D_   1024
#define H_   16
#define KV_  4
#define HD_  64
#define KVD_ 256
#define FF_  4096
#define L_   8
#define V_   50257
#define VPAD_ 50304
#define QKVD_ 1536
#define EPS_ 1.1920928955078125e-07f

// ---------------- device globals ----------------
__device__ __nv_bfloat16 g_qw  [L_ * QKVD_ * D_];
__device__ __nv_bfloat16 g_qwo [L_ * D_   * D_ ];
__device__ __nv_bfloat16 g_qwfc[L_ * FF_  * D_ ];
__device__ __nv_bfloat16 g_qwpr[L_ * D_   * FF_];
__device__ __half        g_qlmh[(size_t)VPAD_ * D_];
__device__ float g_sqkv[L_ * QKVD_];
__device__ float g_swo [L_ * D_ ];
__device__ float g_swfc[L_ * FF_];
__device__ float g_swpr[L_ * D_ ];
__device__ float g_slm [VPAD_];

__device__ float g_x  [S_ * D_ ];
__device__ __nv_bfloat16 g_hhi[S_ * D_ ];
__device__ __nv_bfloat16 g_hlo[S_ * D_ ];
__device__ __half        g_h16[S_ * D_ ];
__device__ float g_qkv[S_ * QKVD_];
__device__ __nv_bfloat16 g_atthi[S_ * D_];
__device__ __nv_bfloat16 g_attlo[S_ * D_];
__device__ __nv_bfloat16 g_ffhi [S_ * FF_];
__device__ __nv_bfloat16 g_fflo [S_ * FF_];

__device__ __nv_bfloat16 g_qhi [S_ * D_ ];
__device__ __nv_bfloat16 g_qlo [S_ * D_ ];
__device__ __nv_bfloat16 g_khi [S_ * KVD_];
__device__ __nv_bfloat16 g_klo [S_ * KVD_];
__device__ __nv_bfloat16 g_vthi[KVD_ * S_];
__device__ __nv_bfloat16 g_vtlo[KVD_ * S_];

// ---------------- helpers ----------------
__device__ __forceinline__ u32 smem_u32(const void* p) {
    return (u32)__cvta_generic_to_shared(p);
}
__device__ __forceinline__ void cpasync16(u32 dst, const void* src) {
    asm volatile("cp.async.cg.shared.global [%0], [%1], 16;" :: "r"(dst), "l"(src));
}
__device__ __forceinline__ void ldm_x4(u32& r0, u32& r1, u32& r2, u32& r3, u32 a) {
    asm volatile("ldmatrix.sync.aligned.m8n8.x4.shared.b16 {%0,%1,%2,%3}, [%4];"
        : "=r"(r0), "=r"(r1), "=r"(r2), "=r"(r3) : "r"(a));
}
__device__ __forceinline__ void mma16816(float* d, const u32* a, const u32* b) {
    asm volatile("mma.sync.aligned.m16n8k16.row.col.f32.bf16.bf16.f32 "
        "{%0,%1,%2,%3}, {%4,%5,%6,%7}, {%8,%9}, {%0,%1,%2,%3};"
        : "+f"(d[0]), "+f"(d[1]), "+f"(d[2]), "+f"(d[3])
        : "r"(a[0]), "r"(a[1]), "r"(a[2]), "r"(a[3]), "r"(b[0]), "r"(b[1]));
}
__device__ __forceinline__ void mma16816h(float* d, const u32* a, const u32* b) {
    asm volatile("mma.sync.aligned.m16n8k16.row.col.f32.f16.f16.f32 "
        "{%0,%1,%2,%3}, {%4,%5,%6,%7}, {%8,%9}, {%0,%1,%2,%3};"
        : "+f"(d[0]), "+f"(d[1]), "+f"(d[2]), "+f"(d[3])
        : "r"(a[0]), "r"(a[1]), "r"(a[2]), "r"(a[3]), "r"(b[0]), "r"(b[1]));
}
__device__ __forceinline__ u32 sw128(u32 b) {
    return b ^ ((b >> 3) & 0x70u);
}
__device__ __forceinline__ void split_store(float v, __nv_bfloat16* hi, __nv_bfloat16* lo, size_t i) {
    __nv_bfloat16 h = __float2bfloat16(v);
    hi[i] = h;
    lo[i] = __float2bfloat16(v - __bfloat162float(h));
}
__device__ __forceinline__ void split2(float a, float b, u32& hi, u32& lo) {
    __nv_bfloat16 ha = __float2bfloat16(a), hb = __float2bfloat16(b);
    hi = (u32)__bfloat16_as_ushort(ha) | ((u32)__bfloat16_as_ushort(hb) << 16);
    lo = (u32)__bfloat16_as_ushort(__float2bfloat16(a - __bfloat162float(ha)))
       | ((u32)__bfloat16_as_ushort(__float2bfloat16(b - __bfloat162float(hb))) << 16);
}
// branchless two-max update: m1 = max, m2 = second max
__device__ __forceinline__ void max2_upd(float& m1, float& m2, float a) {
    float t = fminf(m1, a);
    m1 = fmaxf(m1, a);
    m2 = fmaxf(m2, t);
}

template<int W> __device__ __forceinline__ __nv_bfloat16* qsel() {
    if (W == 0) return g_qw;
    if (W == 1) return g_qwo;
    if (W == 2) return g_qwfc;
    return g_qwpr;
}
template<int W> __device__ __forceinline__ float* scsel() {
    if (W == 0) return g_sqkv;
    if (W == 1) return g_swo;
    if (W == 2) return g_swfc;
    if (W == 3) return g_swpr;
    return g_slm;
}
template<int A> __device__ __forceinline__ const __nv_bfloat16* ahisel() {
    if (A == 0) return g_hhi;
    if (A == 1) return g_atthi;
    return g_ffhi;
}
template<int A> __device__ __forceinline__ const __nv_bfloat16* alosel() {
    if (A == 0) return g_hlo;
    if (A == 1) return g_attlo;
    return g_fflo;
}

// ---------------- fake-quant (bf16 outputs, layer weights) ----------------
template<int WSEL, int NR>
__global__ void quant_kernel(const float* __restrict__ W, int rpl, int ld, int off)
{
    const int n = NR * 256;
    int blk = blockIdx.x;
    int l = blk / rpl, r = blk % rpl;
    int out_row = l * ld + off + r;
    const float* w = W + (size_t)blk * n;
    __nv_bfloat16* qb = qsel<WSEL>() + (size_t)out_row * n;
    int tid = threadIdx.x;

    float v[NR];
    float m1 = 0.f, m2 = 0.f;
    #pragma unroll
    for (int j = 0; j < NR; j++) {
        v[j] = w[tid + j * 256];
        max2_upd(m1, m2, fabsf(v[j]));
    }
    __shared__ float s1[256], s2[256];
    s1[tid] = m1; s2[tid] = m2;
    __syncthreads();
    for (int o = 128; o; o >>= 1) {
        if (tid < o) {
            float a1 = s1[tid], b1 = s1[tid + o];
            float c2 = fmaxf(s2[tid], s2[tid + o]);
            s1[tid] = fmaxf(a1, b1);
            s2[tid] = fmaxf(fminf(a1, b1), c2);
        }
        __syncthreads();
    }
    __shared__ float sh_clip, sh_scale;
    if (tid == 0) {
        float M1 = s1[0], M2 = s2[0];
        float idxf = 0.9999984f * (float)(n - 1);
        float frac = idxf - (float)(n - 2);
        float clip = M2 * (1.0f - frac) + M1 * frac;
        float scale = fmaxf(__fdiv_rn(clip, 127.0f), 1.0f / 127.0f);
        sh_clip = clip;
        sh_scale = scale;
        scsel<WSEL>()[out_row] = __half2float(__float2half_rn(scale));
    }
    __syncthreads();
    float clip = sh_clip, scale = sh_scale;
    #pragma unroll
    for (int j = 0; j < NR; j++) {
        float c = fminf(fmaxf(v[j], -clip), clip);
        float q = rintf(__fdiv_rn(c, scale));
        q = fminf(fmaxf(q, -127.f), 127.f);
        qb[tid + j * 256] = __float2bfloat16(q);
    }
}

// ---------------- fake-quant (fp16 output, lm_head) ----------------
__global__ void quant_lmh_kernel(const float* __restrict__ W)
{
    const int n = D_;
    int out_row = blockIdx.x;
    const float* w = W + (size_t)out_row * n;
    __half* qb = g_qlmh + (size_t)out_row * n;
    int tid = threadIdx.x;

    float v[4];
    float m1 = 0.f, m2 = 0.f;
    #pragma unroll
    for (int j = 0; j < 4; j++) {
        v[j] = w[tid + j * 256];
        max2_upd(m1, m2, fabsf(v[j]));
    }
    __shared__ float s1[256], s2[256];
    s1[tid] = m1; s2[tid] = m2;
    __syncthreads();
    for (int o = 128; o; o >>= 1) {
        if (tid < o) {
            float a1 = s1[tid], b1 = s1[tid + o];
            float c2 = fmaxf(s2[tid], s2[tid + o]);
            s1[tid] = fmaxf(a1, b1);
            s2[tid] = fmaxf(fminf(a1, b1), c2);
        }
        __syncthreads();
    }
    __shared__ float sh_clip, sh_scale;
    if (tid == 0) {
        float M1 = s1[0], M2 = s2[0];
        float idxf = 0.9999984f * (float)(n - 1);
        float frac = idxf - (float)(n - 2);
        float clip = M2 * (1.0f - frac) + M1 * frac;
        float scale = fmaxf(__fdiv_rn(clip, 127.0f), 1.0f / 127.0f);
        sh_clip = clip;
        sh_scale = scale;
        g_slm[out_row] = __half2float(__float2half_rn(scale));
    }
    __syncthreads();
    float clip = sh_clip, scale = sh_scale;
    #pragma unroll
    for (int j = 0; j < 4; j++) {
        float c = fminf(fmaxf(v[j], -clip), clip);
        float q = rintf(__fdiv_rn(c, scale));
        q = fminf(fmaxf(q, -127.f), 127.f);
        qb[tid + j * 256] = __float2half_rn(q);
    }
}

// ---------------- embedding ----------------
__global__ void embed_kernel(const int* __restrict__ idx, const float* __restrict__ emb)
{
    int i = blockIdx.x * blockDim.x + threadIdx.x;
    int s = i >> 10, d = i & 1023;
    g_x[i] = emb[(size_t)idx[s] * D_ + d];
}

// ---------------- rmsnorm -> bf16 hi/lo ----------------
__global__ void rmsnorm_split_kernel()
{
    int row = blockIdx.x;
    const float* xr = g_x + (size_t)row * D_;
    int tid = threadIdx.x;
    float ss = 0.f;
    for (int i = tid; i < D_; i += 256) { float v = xr[i]; ss += v * v; }
    __shared__ float sh[256];
    sh[tid] = ss; __syncthreads();
    for (int o = 128; o; o >>= 1) {
        if (tid < o) sh[tid] += sh[tid + o];
        __syncthreads();
    }
    float r = rsqrtf(sh[0] / (float)D_ + EPS_);
    for (int i = tid; i < D_; i += 256) {
        split_store(xr[i] * r, g_hhi, g_hlo, (size_t)row * D_ + i);
    }
}

// ---------------- final rmsnorm -> fp16 ----------------
__global__ void rmsnorm_h_kernel()
{
    int row = blockIdx.x;
    const float* xr = g_x + (size_t)row * D_;
    int tid = threadIdx.x;
    float ss = 0.f;
    for (int i = tid; i < D_; i += 256) { float v = xr[i]; ss += v * v; }
    __shared__ float sh[256];
    sh[tid] = ss; __syncthreads();
    for (int o = 128; o; o >>= 1) {
        if (tid < o) sh[tid] += sh[tid + o];
        __syncthreads();
    }
    float r = rsqrtf(sh[0] / (float)D_ + EPS_);
    for (int i = tid; i < D_; i += 256) {
        g_h16[(size_t)row * D_ + i] = __float2half_rn(xr[i] * r);
    }
}

// ---------------- merged per-head RMS + RoPE + gain ----------------
__global__ void qkpost_kernel(const float* __restrict__ gain)
{
    int warp = (blockIdx.x * blockDim.x + threadIdx.x) >> 5;
    int lane = threadIdx.x & 31;
    int s = warp / 20, j = warp % 20;
    if (s >= S_) return;
    int isq = (j < 16);
    int h = isq ? j : j - 16;
    int off = isq ? 0 : 1024;
    const float* base = g_qkv + (size_t)s * QKVD_ + off + h * HD_;
    float e0 = base[lane], e1 = base[lane + 32];
    float ss = e0 * e0 + e1 * e1;
    #pragma unroll
    for (int o = 16; o; o >>= 1) ss += __shfl_xor_sync(0xffffffffu, ss, o);
    float r = rsqrtf(ss * (1.f / 64.f) + EPS_);
    e0 *= r; e1 *= r;
    float inv = (float)exp(-((double)lane / 32.0) * 9.210340371976184);
    float f = (float)s * inv;
    float c  = (float)cos((double)f);
    float sn = (float)sin((double)f);
    float o0 =  e0 * c + e1 * sn;
    float o1 = -e0 * sn + e1 * c;
    if (isq) {
        float g = gain[h] * 0.125f;
        split_store(o0 * g, g_qhi, g_qlo, (size_t)s * D_ + h * HD_ + lane);
        split_store(o1 * g, g_qhi, g_qlo, (size_t)s * D_ + h * HD_ + lane + 32);
    } else {
        split_store(o0, g_khi, g_klo, (size_t)s * KVD_ + h * HD_ + lane);
        split_store(o1, g_khi, g_klo, (size_t)s * KVD_ + h * HD_ + lane + 32);
    }
}

// ---------------- V transpose ----------------
__global__ void vtrans_kernel()
{
    __shared__ float t[32][33];
    int s0 = blockIdx.x * 32, c0 = blockIdx.y * 32;
    int tx = threadIdx.x, ty = threadIdx.y;
    #pragma unroll
    for (int k = 0; k < 32; k += 8)
        t[ty + k][tx] = g_qkv[(size_t)(s0 + ty + k) * QKVD_ + 1280 + c0 + tx];
    __syncthreads();
    #pragma unroll
    for (int k = 0; k < 32; k += 8) {
        float v = t[tx][ty + k];
        split_store(v, g_vthi, g_vtlo, (size_t)(c0 + ty + k) * S_ + s0 + tx);
    }
}

// ---------------- fused flash attention: 128-row Q tiles, 256 threads ----------------
#define FA_DSM (32768 + 2 * 32768 + 1024)

__global__ __launch_bounds__(256, 1) void flash_kernel()
{
    int bi = 7 - (int)blockIdx.x;
    int h = blockIdx.y, kvh = h >> 2;
    extern __shared__ char fsm[];
    u32 base = (smem_u32(fsm) + 1023u) & ~1023u;

    int tid = threadIdx.x, lane = tid & 31, w = tid >> 5;
    int tig = lane & 3, grp = lane >> 2;

    for (int id = tid; id < 1024; id += 256) {
        int r = id >> 3, ck = id & 7;
        u32 so = sw128((u32)(r * 128 + ck * 16));
        size_t gq = (size_t)(bi * 128 + r) * D_ + h * HD_ + ck * 8;
        cpasync16(base + so, g_qhi + gq);
        cpasync16(base + 16384 + so, g_qlo + gq);
    }
    asm volatile("cp.async.commit_group;");

    #define FA_LOAD(st, jt) do { \
        u32 sb_ = base + 32768 + (u32)(st) * 32768; \
        for (int id_ = tid; id_ < 512; id_ += 256) { \
            int r_ = id_ >> 3, ck_ = id_ & 7; \
            u32 so_ = sw128((u32)(r_ * 128 + ck_ * 16)); \
            size_t gk_ = (size_t)((jt) * 64 + r_) * KVD_ + kvh * HD_ + ck_ * 8; \
            cpasync16(sb_ + so_,         g_khi + gk_); \
            cpasync16(sb_ + 8192 + so_,  g_klo + gk_); \
            size_t gv_ = (size_t)(kvh * 64 + r_) * S_ + (jt) * 64 + ck_ * 8; \
            cpasync16(sb_ + 16384 + so_, g_vthi + gv_); \
            cpasync16(sb_ + 24576 + so_, g_vtlo + gv_); \
        } \
        asm volatile("cp.async.commit_group;"); \
    } while (0)

    int n = 2 * bi + 2;
    FA_LOAD(0, 0);

    asm volatile("cp.async.wait_group 1;");
    __syncthreads();
    u32 qh[4][4], ql[4][4];
    #pragma unroll
    for (int kc = 0; kc < 4; kc++) {
        int lr = w * 16 + (lane & 15);
        int ch = kc * 2 + (lane >> 4);
        u32 so = sw128((u32)(lr * 128 + ch * 16));
        ldm_x4(qh[kc][0], qh[kc][1], qh[kc][2], qh[kc][3], base + so);
        ldm_x4(ql[kc][0], ql[kc][1], ql[kc][2], ql[kc][3], base + 16384 + so);
    }

    float o[8][4];
    #pragma unroll
    for (int nd = 0; nd < 8; nd++) { o[nd][0]=0.f; o[nd][1]=0.f; o[nd][2]=0.f; o[nd][3]=0.f; }
    float m0 = -1e30f, m1 = -1e30f, l0 = 0.f, l1 = 0.f;

    for (int jt = 0; jt < n; jt++) {
        if (jt + 1 < n) {
            FA_LOAD((jt + 1) & 1, jt + 1);
            asm volatile("cp.async.wait_group 1;");
        } else {
            asm volatile("cp.async.wait_group 0;");
        }
        __syncthreads();

        u32 kb = base + 32768 + (u32)(jt & 1) * 32768;

        float s[8][4];
        #pragma unroll
        for (int ni = 0; ni < 8; ni++) { s[ni][0]=0.f; s[ni][1]=0.f; s[ni][2]=0.f; s[ni][3]=0.f; }
        #pragma unroll
        for (int kc = 0; kc < 4; kc++) {
            u32 bh[8][2], bl[8][2];
            #pragma unroll
            for (int nj = 0; nj < 4; nj++) {
                int g = lane >> 3;
                int lr = nj * 16 + (((g >> 1) & 1) << 3) + (lane & 7);
                int ch = kc * 2 + (g & 1);
                u32 so = sw128((u32)(lr * 128 + ch * 16));
                u32 r0, r1, r2, r3;
                ldm_x4(r0, r1, r2, r3, kb + so);
                bh[nj * 2][0] = r0; bh[nj * 2][1] = r1;
                bh[nj * 2 + 1][0] = r2; bh[nj * 2 + 1][1] = r3;
                ldm_x4(r0, r1, r2, r3, kb + 8192 + so);
                bl[nj * 2][0] = r0; bl[nj * 2][1] = r1;
                bl[nj * 2 + 1][0] = r2; bl[nj * 2 + 1][1] = r3;
            }
            #pragma unroll
            for (int ni = 0; ni < 8; ni++) {
                mma16816(s[ni], qh[kc], bh[ni]);
                mma16816(s[ni], qh[kc], bl[ni]);
                mma16816(s[ni], ql[kc], bh[ni]);
            }
        }

        if (jt >= 2 * bi) {
            int ci0 = bi * 128 + w * 16 + grp, ci1 = ci0 + 8;
            #pragma unroll
            for (int ni = 0; ni < 8; ni++) {
                int cj = jt * 64 + ni * 8 + tig * 2;
                if (cj     > ci0) s[ni][0] = -1e30f;
                if (cj + 1 > ci0) s[ni][1] = -1e30f;
                if (cj     > ci1) s[ni][2] = -1e30f;
                if (cj + 1 > ci1) s[ni][3] = -1e30f;
            }
        }

        float tm0 = -1e30f, tm1 = -1e30f;
        #pragma unroll
        for (int ni = 0; ni < 8; ni++) {
            tm0 = fmaxf(tm0, fmaxf(s[ni][0], s[ni][1]));
            tm1 = fmaxf(tm1, fmaxf(s[ni][2], s[ni][3]));
        }
        tm0 = fmaxf(tm0, __shfl_xor_sync(0xffffffffu, tm0, 1));
        tm0 = fmaxf(tm0, __shfl_xor_sync(0xffffffffu, tm0, 2));
        tm1 = fmaxf(tm1, __shfl_xor_sync(0xffffffffu, tm1, 1));
        tm1 = fmaxf(tm1, __shfl_xor_sync(0xffffffffu, tm1, 2));
        float mn0 = fmaxf(m0, tm0), mn1 = fmaxf(m1, tm1);
        float a0 = expf(m0 - mn0), a1 = expf(m1 - mn1);
        m0 = mn0; m1 = mn1;

        float rs0 = 0.f, rs1 = 0.f;
        #pragma unroll
        for (int ni = 0; ni < 8; ni++) {
            s[ni][0] = expf(s[ni][0] - mn0);
            s[ni][1] = expf(s[ni][1] - mn0);
            s[ni][2] = expf(s[ni][2] - mn1);
            s[ni][3] = expf(s[ni][3] - mn1);
            rs0 += s[ni][0] + s[ni][1];
            rs1 += s[ni][2] + s[ni][3];
        }
        rs0 += __shfl_xor_sync(0xffffffffu, rs0, 1);
        rs0 += __shfl_xor_sync(0xffffffffu, rs0, 2);
        rs1 += __shfl_xor_sync(0xffffffffu, rs1, 1);
        rs1 += __shfl_xor_sync(0xffffffffu, rs1, 2);
        l0 = l0 * a0 + rs0;
        l1 = l1 * a1 + rs1;
        #pragma unroll
        for (int nd = 0; nd < 8; nd++) {
            o[nd][0] *= a0; o[nd][1] *= a0;
            o[nd][2] *= a1; o[nd][3] *= a1;
        }

        u32 vbh = kb + 16384, vbl = kb + 24576;
        #pragma unroll
        for (int kc = 0; kc < 4; kc++) {
            u32 pah[4], pal[4];
            split2(s[2 * kc][0],     s[2 * kc][1],     pah[0], pal[0]);
            split2(s[2 * kc][2],     s[2 * kc][3],     pah[1], pal[1]);
            split2(s[2 * kc + 1][0], s[2 * kc + 1][1], pah[2], pal[2]);
            split2(s[2 * kc + 1][2], s[2 * kc + 1][3], pah[3], pal[3]);
            u32 vh[8][2], vl[8][2];
            #pragma unroll
            for (int nj = 0; nj < 4; nj++) {
                int g = lane >> 3;
                int lr = nj * 16 + (((g >> 1) & 1) << 3) + (lane & 7);
                int ch = kc * 2 + (g & 1);
                u32 so = sw128((u32)(lr * 128 + ch * 16));
                u32 r0, r1, r2, r3;
                ldm_x4(r0, r1, r2, r3, vbh + so);
                vh[nj * 2][0] = r0; vh[nj * 2][1] = r1;
                vh[nj * 2 + 1][0] = r2; vh[nj * 2 + 1][1] = r3;
                ldm_x4(r0, r1, r2, r3, vbl + so);
                vl[nj * 2][0] = r0; vl[nj * 2][1] = r1;
                vl[nj * 2 + 1][0] = r2; vl[nj * 2 + 1][1] = r3;
            }
            #pragma unroll
            for (int nd = 0; nd < 8; nd++) {
                mma16816(o[nd], pah, vh[nd]);
                mma16816(o[nd], pah, vl[nd]);
                mma16816(o[nd], pal, vh[nd]);
            }
        }
        __syncthreads();
    }

    float inv0 = 1.0f / l0, inv1 = 1.0f / l1;
    int gi0 = bi * 128 + w * 16 + grp;
    #pragma unroll
    for (int nd = 0; nd < 8; nd++) {
        int gd = h * HD_ + nd * 8 + tig * 2;
        split_store(o[nd][0] * inv0, g_atthi, g_attlo, (size_t)gi0 * D_ + gd);
        split_store(o[nd][1] * inv0, g_atthi, g_attlo, (size_t)gi0 * D_ + gd + 1);
        split_store(o[nd][2] * inv1, g_atthi, g_attlo, (size_t)(gi0 + 8) * D_ + gd);
        split_store(o[nd][3] * inv1, g_atthi, g_attlo, (size_t)(gi0 + 8) * D_ + gd + 1);
    }
    #undef FA_LOAD
}

// ---------------- shared GEMM pieces ----------------
template<int BM, int BN>
__device__ __forceinline__ void load_stage64(
    const __nv_bfloat16* Ahi, const __nv_bfloat16* Alo, const __nv_bfloat16* Bq,
    u32 sbase, int row0, int col0, int K, int k0, int tid)
{
    constexpr u32 ABYTES = (u32)BM * 128;
    for (int id = tid; id < BM * 8; id += 256) {
        int r = id >> 3, ck = id & 7;
        u32 so = sw128((u32)(r * 128 + ck * 16));
        size_t g = (size_t)(row0 + r) * K + k0 + ck * 8;
        cpasync16(sbase + so, Ahi + g);
        cpasync16(sbase + ABYTES + so, Alo + g);
    }
    for (int id = tid; id < BN * 8; id += 256) {
        int r = id >> 3, ck = id & 7;
        u32 so = sw128((u32)(r * 128 + ck * 16));
        cpasync16(sbase + 2 * ABYTES + so, Bq + (size_t)(col0 + r) * K + k0 + ck * 8);
    }
    asm volatile("cp.async.commit_group;");
}

template<int EPI>
__device__ __forceinline__ void epi_store(float v, int gr, int c, float* Cout, int ldc)
{
    if (EPI == 0) {
        g_qkv[(size_t)gr * QKVD_ + c] = v;
    } else if (EPI == 1) {
        g_x[(size_t)gr * D_ + c] += v;
    } else if (EPI == 2) {
        float t = fmaxf(v, 0.f);
        split_store(t * t, g_ffhi, g_fflo, (size_t)gr * FF_ + c);
    } else {
        Cout[(size_t)gr * ldc + c] = v;
    }
}

// ---------------- small GEMM: 128x64, 2-stage, 2 CTAs/SM ----------------
template<int EPI, int WSEL, int ASEL>
__global__ __launch_bounds__(256, 2)
void qgemm2_kernel(float* __restrict__ Cout, int layer, int N, int K, int ldc)
{
    constexpr int BM = 128, BN = 64;
    constexpr int MI = 2, NI = 4;
    constexpr u32 STB = (u32)(2 * BM + BN) * 128;

    extern __shared__ char dsm[];
    u32 base = (smem_u32(dsm) + 1023u) & ~1023u;

    int tid = threadIdx.x, lane = tid & 31, wid = tid >> 5;
    int wm = wid % 4, wn = wid / 4;
    int row0 = blockIdx.y * BM, col0 = blockIdx.x * BN;

    const __nv_bfloat16* Ahi = ahisel<ASEL>();
    const __nv_bfloat16* Alo = alosel<ASEL>();
    const __nv_bfloat16* Bq  = qsel<WSEL>() + (size_t)layer * N * K;
    const float* Sc = scsel<WSEL>() + (size_t)layer * N;

    float acc[MI][NI][4];
    #pragma unroll
    for (int mi = 0; mi < MI; mi++)
        #pragma unroll
        for (int ni = 0; ni < NI; ni++) {
            acc[mi][ni][0] = 0.f; acc[mi][ni][1] = 0.f;
            acc[mi][ni][2] = 0.f; acc[mi][ni][3] = 0.f;
        }

    int n = K >> 6;
    load_stage64<BM, BN>(Ahi, Alo, Bq, base,       row0, col0, K, 0,  tid);
    load_stage64<BM, BN>(Ahi, Alo, Bq, base + STB, row0, col0, K, 64, tid);

    for (int it = 0; it < n; it++) {
        if (it + 1 < n) { asm volatile("cp.async.wait_group 1;"); }
        else            { asm volatile("cp.async.wait_group 0;"); }
        __syncthreads();

        u32 sb = base + (u32)(it & 1) * STB;
        #pragma unroll
        for (int kc = 0; kc < 4; kc++) {
            u32 ah[MI][4], al[MI][4];
            #pragma unroll
            for (int mi = 0; mi < MI; mi++) {
                int lr = wm * 32 + mi * 16 + (lane & 15);
                int ch = kc * 2 + (lane >> 4);
                u32 so = sw128((u32)(lr * 128 + ch * 16));
                ldm_x4(ah[mi][0], ah[mi][1], ah[mi][2], ah[mi][3], sb + so);
                ldm_x4(al[mi][0], al[mi][1], al[mi][2], al[mi][3], sb + (u32)BM * 128 + so);
            }
            u32 bb[NI][2];
            #pragma unroll
            for (int nj = 0; nj < NI / 2; nj++) {
                int g = lane >> 3;
                int lr = wn * 32 + nj * 16 + (((g >> 1) & 1) << 3) + (lane & 7);
                int ch = kc * 2 + (g & 1);
                u32 r0, r1, r2, r3;
                ldm_x4(r0, r1, r2, r3, sb + 2u * BM * 128 + sw128((u32)(lr * 128 + ch * 16)));
                bb[nj * 2][0] = r0; bb[nj * 2][1] = r1;
                bb[nj * 2 + 1][0] = r2; bb[nj * 2 + 1][1] = r3;
            }
            #pragma unroll
            for (int mi = 0; mi < MI; mi++)
                #pragma unroll
                for (int ni = 0; ni < NI; ni++) {
                    mma16816(acc[mi][ni], ah[mi], bb[ni]);
                    mma16816(acc[mi][ni], al[mi], bb[ni]);
                }
        }
        __syncthreads();
        if (it + 2 < n)
            load_stage64<BM, BN>(Ahi, Alo, Bq, base + (u32)(it & 1) * STB,
                                 row0, col0, K, (it + 2) << 6, tid);
    }

    #pragma unroll
    for (int mi = 0; mi < MI; mi++) {
        #pragma unroll
        for (int ni = 0; ni < NI; ni++) {
            int gr0 = row0 + wm * 32 + mi * 16 + (lane >> 2);
            int gc  = col0 + wn * 32 + ni * 8 + ((lane & 3) << 1);
            #pragma unroll
            for (int half = 0; half < 2; half++) {
                int gr = gr0 + half * 8;
                #pragma unroll
                for (int e = 0; e < 2; e++) {
                    int c = gc + e;
                    if (c >= N) continue;
                    epi_store<EPI>(acc[mi][ni][half * 2 + e] * Sc[c], gr, c, Cout, ldc);
                }
            }
        }
    }
}

// ---------------- big GEMM: 128x128, 3-stage (bf16 hi/lo) ----------------
template<int EPI, int WSEL, int ASEL>
__global__ __launch_bounds__(256, 1)
void qgemm3_kernel(float* __restrict__ Cout, int layer, int N, int K, int ldc)
{
    constexpr int BM = 128, BN = 128;
    constexpr int MI = 4, NI = 4;
    constexpr u32 STB = (u32)(2 * BM + BN) * 128;

    extern __shared__ char dsm[];
    u32 base = (smem_u32(dsm) + 1023u) & ~1023u;

    int tid = threadIdx.x, lane = tid & 31, wid = tid >> 5;
    int wm = wid % 2, wn = wid / 2;
    int row0 = blockIdx.y * BM, col0 = blockIdx.x * BN;

    const __nv_bfloat16* Ahi = ahisel<ASEL>();
    const __nv_bfloat16* Alo = alosel<ASEL>();
    const __nv_bfloat16* Bq  = qsel<WSEL>() + (size_t)layer * N * K;
    const float* Sc = scsel<WSEL>() + (size_t)layer * N;

    float acc[MI][NI][4];
    #pragma unroll
    for (int mi = 0; mi < MI; mi++)
        #pragma unroll
        for (int ni = 0; ni < NI; ni++) {
            acc[mi][ni][0] = 0.f; acc[mi][ni][1] = 0.f;
            acc[mi][ni][2] = 0.f; acc[mi][ni][3] = 0.f;
        }

    int n = K >> 6;
    load_stage64<BM, BN>(Ahi, Alo, Bq, base,       row0, col0, K, 0,  tid);
    load_stage64<BM, BN>(Ahi, Alo, Bq, base + STB, row0, col0, K, 64, tid);

    for (int it = 0; it < n; it++) {
        asm volatile("cp.async.wait_group 1;");
        __syncthreads();

        int ldst = it + 2;
        if (ldst < n) {
            load_stage64<BM, BN>(Ahi, Alo, Bq, base + (u32)(ldst % 3) * STB,
                                 row0, col0, K, ldst << 6, tid);
        } else {
            asm volatile("cp.async.commit_group;");
        }

        u32 sb = base + (u32)(it % 3) * STB;
        #pragma unroll
        for (int kc = 0; kc < 4; kc++) {
            u32 ah[MI][4], al[MI][4];
            #pragma unroll
            for (int mi = 0; mi < MI; mi++) {
                int lr = wm * 64 + mi * 16 + (lane & 15);
                int ch = kc * 2 + (lane >> 4);
                u32 so = sw128((u32)(lr * 128 + ch * 16));
                ldm_x4(ah[mi][0], ah[mi][1], ah[mi][2], ah[mi][3], sb + so);
                ldm_x4(al[mi][0], al[mi][1], al[mi][2], al[mi][3], sb + (u32)BM * 128 + so);
            }
            u32 bb[NI][2];
            #pragma unroll
            for (int nj = 0; nj < NI / 2; nj++) {
                int g = lane >> 3;
                int lr = wn * 32 + nj * 16 + (((g >> 1) & 1) << 3) + (lane & 7);
                int ch = kc * 2 + (g & 1);
                u32 r0, r1, r2, r3;
                ldm_x4(r0, r1, r2, r3, sb + 2u * BM * 128 + sw128((u32)(lr * 128 + ch * 16)));
                bb[nj * 2][0] = r0; bb[nj * 2][1] = r1;
                bb[nj * 2 + 1][0] = r2; bb[nj * 2 + 1][1] = r3;
            }
            #pragma unroll
            for (int mi = 0; mi < MI; mi++)
                #pragma unroll
                for (int ni = 0; ni < NI; ni++) {
                    mma16816(acc[mi][ni], ah[mi], bb[ni]);
                    mma16816(acc[mi][ni], al[mi], bb[ni]);
                }
        }
    }

    #pragma unroll
    for (int mi = 0; mi < MI; mi++) {
        #pragma unroll
        for (int ni = 0; ni < NI; ni++) {
            int gr0 = row0 + wm * 64 + mi * 16 + (lane >> 2);
            int gc  = col0 + wn * 32 + ni * 8 + ((lane & 3) << 1);
            #pragma unroll
            for (int half = 0; half < 2; half++) {
                int gr = gr0 + half * 8;
                #pragma unroll
                for (int e = 0; e < 2; e++) {
                    int c = gc + e;
                    if (c >= N) continue;
                    epi_store<EPI>(acc[mi][ni][half * 2 + e] * Sc[c], gr, c, Cout, ldc);
                }
            }
        }
    }
}

// ---------------- lm_head GEMM: 128x128, 3-stage, fp16, L2-friendly grid ----------------
// grid = (rows=8, cols=393): row index varies fastest so concurrent CTAs share B tiles in L2.
__global__ __launch_bounds__(256, 1)
void qgemmh_kernel(float* __restrict__ Cout, int N, int K, int ldc)
{
    constexpr int BM = 128, BN = 128;
    constexpr int MI = 4, NI = 4;
    constexpr u32 STB = (u32)(BM + BN) * 128;   // 32768

    extern __shared__ char dsm[];
    u32 base = (smem_u32(dsm) + 1023u) & ~1023u;

    int tid = threadIdx.x, lane = tid & 31, wid = tid >> 5;
    int wm = wid % 2, wn = wid / 2;
    int row0 = blockIdx.x * BM, col0 = blockIdx.y * BN;   // transposed grid

    const __half* A = g_h16;
    const __half* Bq = g_qlmh;
    const float* Sc = g_slm;

    float acc[MI][NI][4];
    #pragma unroll
    for (int mi = 0; mi < MI; mi++)
        #pragma unroll
        for (int ni = 0; ni < NI; ni++) {
            acc[mi][ni][0] = 0.f; acc[mi][ni][1] = 0.f;
            acc[mi][ni][2] = 0.f; acc[mi][ni][3] = 0.f;
        }

    #define LMLOAD(sbase, k0) do { \
        for (int id = tid; id < BM * 8; id += 256) { \
            int r = id >> 3, ck = id & 7; \
            u32 so = sw128((u32)(r * 128 + ck * 16)); \
            cpasync16((sbase) + so, A + (size_t)(row0 + r) * K + (k0) + ck * 8); \
        } \
        for (int id = tid; id < BN * 8; id += 256) { \
            int r = id >> 3, ck = id & 7; \
            u32 so = sw128((u32)(r * 128 + ck * 16)); \
            cpasync16((sbase) + (u32)BM * 128 + so, Bq + (size_t)(col0 + r) * K + (k0) + ck * 8); \
        } \
        asm volatile("cp.async.commit_group;"); \
    } while (0)

    int n = K >> 6;
    LMLOAD(base, 0);
    LMLOAD(base + STB, 64);

    for (int it = 0; it < n; it++) {
        asm volatile("cp.async.wait_group 1;");
        __syncthreads();

        int ldst = it + 2;
        if (ldst < n) {
            LMLOAD(base + (u32)(ldst % 3) * STB, ldst << 6);
        } else {
            asm volatile("cp.async.commit_group;");
        }

        u32 sb = base + (u32)(it % 3) * STB;
        #pragma unroll
        for (int kc = 0; kc < 4; kc++) {
            u32 ah[MI][4];
            #pragma unroll
            for (int mi = 0; mi < MI; mi++) {
                int lr = wm * 64 + mi * 16 + (lane & 15);
                int ch = kc * 2 + (lane >> 4);
                u32 so = sw128((u32)(lr * 128 + ch * 16));
                ldm_x4(ah[mi][0], ah[mi][1], ah[mi][2], ah[mi][3], sb + so);
            }
            u32 bb[NI][2];
            #pragma unroll
            for (int nj = 0; nj < NI / 2; nj++) {
                int g = lane >> 3;
                int lr = wn * 32 + nj * 16 + (((g >> 1) & 1) << 3) + (lane & 7);
                int ch = kc * 2 + (g & 1);
                u32 r0, r1, r2, r3;
                ldm_x4(r0, r1, r2, r3, sb + (u32)BM * 128 + sw128((u32)(lr * 128 + ch * 16)));
                bb[nj * 2][0] = r0; bb[nj * 2][1] = r1;
                bb[nj * 2 + 1][0] = r2; bb[nj * 2 + 1][1] = r3;
            }
            #pragma unroll
            for (int mi = 0; mi < MI; mi++)
                #pragma unroll
                for (int ni = 0; ni < NI; ni++)
                    mma16816h(acc[mi][ni], ah[mi], bb[ni]);
        }
    }
    #undef LMLOAD

    #pragma unroll
    for (int mi = 0; mi < MI; mi++) {
        #pragma unroll
        for (int ni = 0; ni < NI; ni++) {
            int gr0 = row0 + wm * 64 + mi * 16 + (lane >> 2);
            int gc  = col0 + wn * 32 + ni * 8 + ((lane & 3) << 1);
            #pragma unroll
            for (int half = 0; half < 2; half++) {
                int gr = gr0 + half * 8;
                #pragma unroll
                for (int e = 0; e < 2; e++) {
                    int c = gc + e;
                    if (c >= N) continue;
                    Cout[(size_t)gr * ldc + c] = acc[mi][ni][half * 2 + e] * Sc[c];
                }
            }
        }
    }
}

#define DSM_SMALL (2 * (2 * 128 + 64)  * 128 + 1024)
#define DSM_BIG   (3 * (2 * 128 + 128) * 128 + 1024)
#define DSM_LM    (3 * (128 + 128) * 128 + 1024)

// ---------------- host orchestration ----------------
extern "C" void kernel_launch(void* const* d_in, const int* in_sizes, int n_in,
                              void* d_out, int out_size)
{
    (void)in_sizes; (void)n_in; (void)out_size;
    const int*   idx = (const int*)  d_in[0];
    const float* emb = (const float*)d_in[1];
    const float* wq  = (const float*)d_in[2];
    const float* wk  = (const float*)d_in[3];
    const float* wv  = (const float*)d_in[4];
    const float* wo  = (const float*)d_in[5];
    const float* qg  = (const float*)d_in[6];
    const float* wfc = (const float*)d_in[7];
    const float* wpr = (const float*)d_in[8];
    const float* lm  = (const float*)d_in[9];
    float* out = (float*)d_out;

    cudaFuncSetAttribute(qgemm2_kernel<0, 0, 0>,
                         cudaFuncAttributeMaxDynamicSharedMemorySize, DSM_SMALL);
    cudaFuncSetAttribute(qgemm2_kernel<1, 1, 1>,
                         cudaFuncAttributeMaxDynamicSharedMemorySize, DSM_SMALL);
    cudaFuncSetAttribute(qgemm2_kernel<1, 3, 2>,
                         cudaFuncAttributeMaxDynamicSharedMemorySize, DSM_SMALL);
    cudaFuncSetAttribute(qgemm3_kernel<2, 2, 0>,
                         cudaFuncAttributeMaxDynamicSharedMemorySize, DSM_BIG);
    cudaFuncSetAttribute(qgemmh_kernel,
                         cudaFuncAttributeMaxDynamicSharedMemorySize, DSM_LM);
    cudaFuncSetAttribute(flash_kernel,
                         cudaFuncAttributeMaxDynamicSharedMemorySize, FA_DSM);

    quant_kernel<0, 4><<<L_ * D_,    256>>>(wq,  D_,   QKVD_, 0);
    quant_kernel<0, 4><<<L_ * KVD_,  256>>>(wk,  KVD_, QKVD_, 1024);
    quant_kernel<0, 4><<<L_ * KVD_,  256>>>(wv,  KVD_, QKVD_, 1280);
    quant_kernel<1, 4><<<L_ * D_,    256>>>(wo,  L_ * D_,  0, 0);
    quant_kernel<2, 4><<<L_ * FF_,   256>>>(wfc, L_ * FF_, 0, 0);
    quant_kernel<3, 16><<<L_ * D_,   256>>>(wpr, L_ * D_,  0, 0);
    quant_lmh_kernel<<<V_,           256>>>(lm);

    embed_kernel<<<(S_ * D_) / 256, 256>>>(idx, emb);

    for (int l = 0; l < L_; l++) {
        rmsnorm_split_kernel<<<S_, 256>>>();

        qgemm2_kernel<0, 0, 0><<<dim3(QKVD_ / 64, S_ / 128), 256, DSM_SMALL>>>(
            nullptr, l, QKVD_, D_, QKVD_);

        qkpost_kernel<<<(S_ * 20) / 4, 128>>>(qg + l * H_);
        vtrans_kernel<<<dim3(S_ / 32, KVD_ / 32), dim3(32, 8)>>>();

        flash_kernel<<<dim3(8, H_), 256, FA_DSM>>>();

        qgemm2_kernel<1, 1, 1><<<dim3(D_ / 64, S_ / 128), 256, DSM_SMALL>>>(
            nullptr, l, D_, D_, D_);

        rmsnorm_split_kernel<<<S_, 256>>>();

        qgemm3_kernel<2, 2, 0><<<dim3(FF_ / 128, S_ / 128), 256, DSM_BIG>>>(
            nullptr, l, FF_, D_, FF_);

        qgemm2_kernel<1, 3, 2><<<dim3(D_ / 64, S_ / 128), 256, DSM_SMALL>>>(
            nullptr, l, D_, FF_, D_);
    }

    // final norm (fp16) + fp16 lm_head with transposed (L2-friendly) grid
    rmsnorm_h_kernel<<<S_, 256>>>();
    qgemmh_kernel<<<dim3(S_ / 128, VPAD_ / 128), 256, DSM_LM>>>(
        out, V_, D_, V_);
}

// round 16
// speedup vs baseline: 1.1705x; 1.1705x over previous
#include <cuda_runtime.h>
#include <cuda_fp16.h>
#include <cuda_bf16.h>
#include <stdint.h>
#include <cstdint>
#include <math.h>
#include <float.h>

typedef unsigned int u32;

#define S_   1024
#define D_   1024
#define H_   16
#define KV_  4
#define HD_  64
#define KVD_ 256
#define FF_  4096
#define L_   8
#define V_   50257
#define VPAD_ 50304
#define QKVD_ 1536
#define EPS_ 1.1920928955078125e-07f

// ---------------- device globals ----------------
// fp16 weights (exact small integers) + per-row scales
__device__ __half g_qw16  [L_ * QKVD_ * D_];
__device__ __half g_qwo16 [L_ * D_   * D_ ];
__device__ __half g_qwfc16[L_ * FF_  * D_ ];
__device__ __half g_qwpr16[L_ * D_   * FF_];
__device__ __half g_qlmh  [(size_t)VPAD_ * D_];
__device__ float g_sqkv[L_ * QKVD_];
__device__ float g_swo [L_ * D_ ];
__device__ float g_swfc[L_ * FF_];
__device__ float g_swpr[L_ * D_ ];
__device__ float g_slm [VPAD_];

__device__ float g_x  [S_ * D_ ];
__device__ __half g_h16[S_ * D_ ];     // rmsnorm out (fp16 single)
__device__ __half g_a16[S_ * D_ ];     // attention out
__device__ __half g_f16[S_ * FF_];     // relu^2 out
__device__ float g_qkv[S_ * QKVD_];

// flash attention operands (bf16 hi/lo, unchanged)
__device__ __nv_bfloat16 g_qhi [S_ * D_ ];
__device__ __nv_bfloat16 g_qlo [S_ * D_ ];
__device__ __nv_bfloat16 g_khi [S_ * KVD_];
__device__ __nv_bfloat16 g_klo [S_ * KVD_];
__device__ __nv_bfloat16 g_vthi[KVD_ * S_];
__device__ __nv_bfloat16 g_vtlo[KVD_ * S_];

// ---------------- helpers ----------------
__device__ __forceinline__ u32 smem_u32(const void* p) {
    return (u32)__cvta_generic_to_shared(p);
}
__device__ __forceinline__ void cpasync16(u32 dst, const void* src) {
    asm volatile("cp.async.cg.shared.global [%0], [%1], 16;" :: "r"(dst), "l"(src));
}
__device__ __forceinline__ void ldm_x4(u32& r0, u32& r1, u32& r2, u32& r3, u32 a) {
    asm volatile("ldmatrix.sync.aligned.m8n8.x4.shared.b16 {%0,%1,%2,%3}, [%4];"
        : "=r"(r0), "=r"(r1), "=r"(r2), "=r"(r3) : "r"(a));
}
__device__ __forceinline__ void mma16816(float* d, const u32* a, const u32* b) {
    asm volatile("mma.sync.aligned.m16n8k16.row.col.f32.bf16.bf16.f32 "
        "{%0,%1,%2,%3}, {%4,%5,%6,%7}, {%8,%9}, {%0,%1,%2,%3};"
        : "+f"(d[0]), "+f"(d[1]), "+f"(d[2]), "+f"(d[3])
        : "r"(a[0]), "r"(a[1]), "r"(a[2]), "r"(a[3]), "r"(b[0]), "r"(b[1]));
}
__device__ __forceinline__ void mma16816h(float* d, const u32* a, const u32* b) {
    asm volatile("mma.sync.aligned.m16n8k16.row.col.f32.f16.f16.f32 "
        "{%0,%1,%2,%3}, {%4,%5,%6,%7}, {%8,%9}, {%0,%1,%2,%3};"
        : "+f"(d[0]), "+f"(d[1]), "+f"(d[2]), "+f"(d[3])
        : "r"(a[0]), "r"(a[1]), "r"(a[2]), "r"(a[3]), "r"(b[0]), "r"(b[1]));
}
__device__ __forceinline__ u32 sw128(u32 b) {
    return b ^ ((b >> 3) & 0x70u);
}
__device__ __forceinline__ void split_store(float v, __nv_bfloat16* hi, __nv_bfloat16* lo, size_t i) {
    __nv_bfloat16 h = __float2bfloat16(v);
    hi[i] = h;
    lo[i] = __float2bfloat16(v - __bfloat162float(h));
}
__device__ __forceinline__ void split2(float a, float b, u32& hi, u32& lo) {
    __nv_bfloat16 ha = __float2bfloat16(a), hb = __float2bfloat16(b);
    hi = (u32)__bfloat16_as_ushort(ha) | ((u32)__bfloat16_as_ushort(hb) << 16);
    lo = (u32)__bfloat16_as_ushort(__float2bfloat16(a - __bfloat162float(ha)))
       | ((u32)__bfloat16_as_ushort(__float2bfloat16(b - __bfloat162float(hb))) << 16);
}
__device__ __forceinline__ void max2_upd(float& m1, float& m2, float a) {
    float t = fminf(m1, a);
    m1 = fmaxf(m1, a);
    m2 = fmaxf(m2, t);
}

template<int W> __device__ __forceinline__ __half* qsel() {
    if (W == 0) return g_qw16;
    if (W == 1) return g_qwo16;
    if (W == 2) return g_qwfc16;
    if (W == 3) return g_qwpr16;
    return g_qlmh;
}
template<int W> __device__ __forceinline__ float* scsel() {
    if (W == 0) return g_sqkv;
    if (W == 1) return g_swo;
    if (W == 2) return g_swfc;
    if (W == 3) return g_swpr;
    return g_slm;
}
template<int A> __device__ __forceinline__ const __half* a16sel() {
    if (A == 0) return g_h16;
    if (A == 1) return g_a16;
    return g_f16;
}

// ---------------- fake-quant: per-row top-2 abs -> clip -> q (fp16 int) + scale ----------------
template<int WSEL, int NR>
__global__ void quant_kernel(const float* __restrict__ W, int rpl, int ld, int off)
{
    const int n = NR * 256;
    int blk = blockIdx.x;
    int l = blk / rpl, r = blk % rpl;
    int out_row = l * ld + off + r;
    const float* w = W + (size_t)blk * n;
    __half* qb = qsel<WSEL>() + (size_t)out_row * n;
    int tid = threadIdx.x;

    float v[NR];
    float m1 = 0.f, m2 = 0.f;
    #pragma unroll
    for (int j = 0; j < NR; j++) {
        v[j] = w[tid + j * 256];
        max2_upd(m1, m2, fabsf(v[j]));
    }
    __shared__ float s1[256], s2[256];
    s1[tid] = m1; s2[tid] = m2;
    __syncthreads();
    for (int o = 128; o; o >>= 1) {
        if (tid < o) {
            float a1 = s1[tid], b1 = s1[tid + o];
            float c2 = fmaxf(s2[tid], s2[tid + o]);
            s1[tid] = fmaxf(a1, b1);
            s2[tid] = fmaxf(fminf(a1, b1), c2);
        }
        __syncthreads();
    }
    __shared__ float sh_clip, sh_scale;
    if (tid == 0) {
        float M1 = s1[0], M2 = s2[0];
        float idxf = 0.9999984f * (float)(n - 1);
        float frac = idxf - (float)(n - 2);
        float clip = M2 * (1.0f - frac) + M1 * frac;
        float scale = fmaxf(__fdiv_rn(clip, 127.0f), 1.0f / 127.0f);
        sh_clip = clip;
        sh_scale = scale;
        scsel<WSEL>()[out_row] = __half2float(__float2half_rn(scale));
    }
    __syncthreads();
    float clip = sh_clip, scale = sh_scale;
    #pragma unroll
    for (int j = 0; j < NR; j++) {
        float c = fminf(fmaxf(v[j], -clip), clip);
        float q = rintf(__fdiv_rn(c, scale));
        q = fminf(fmaxf(q, -127.f), 127.f);
        qb[tid + j * 256] = __float2half_rn(q);   // small integer: exact in fp16
    }
}

// ---------------- embedding ----------------
__global__ void embed_kernel(const int* __restrict__ idx, const float* __restrict__ emb)
{
    int i = blockIdx.x * blockDim.x + threadIdx.x;
    int s = i >> 10, d = i & 1023;
    g_x[i] = emb[(size_t)idx[s] * D_ + d];
}

// ---------------- rmsnorm -> fp16 single ----------------
__global__ void rmsnorm_h_kernel()
{
    int row = blockIdx.x;
    const float* xr = g_x + (size_t)row * D_;
    int tid = threadIdx.x;
    float ss = 0.f;
    for (int i = tid; i < D_; i += 256) { float v = xr[i]; ss += v * v; }
    __shared__ float sh[256];
    sh[tid] = ss; __syncthreads();
    for (int o = 128; o; o >>= 1) {
        if (tid < o) sh[tid] += sh[tid + o];
        __syncthreads();
    }
    float r = rsqrtf(sh[0] / (float)D_ + EPS_);
    for (int i = tid; i < D_; i += 256) {
        g_h16[(size_t)row * D_ + i] = __float2half_rn(xr[i] * r);
    }
}

// ---------------- merged per-head RMS + RoPE + gain (bf16 hi/lo for flash) ----------------
__global__ void qkpost_kernel(const float* __restrict__ gain)
{
    int warp = (blockIdx.x * blockDim.x + threadIdx.x) >> 5;
    int lane = threadIdx.x & 31;
    int s = warp / 20, j = warp % 20;
    if (s >= S_) return;
    int isq = (j < 16);
    int h = isq ? j : j - 16;
    int off = isq ? 0 : 1024;
    const float* base = g_qkv + (size_t)s * QKVD_ + off + h * HD_;
    float e0 = base[lane], e1 = base[lane + 32];
    float ss = e0 * e0 + e1 * e1;
    #pragma unroll
    for (int o = 16; o; o >>= 1) ss += __shfl_xor_sync(0xffffffffu, ss, o);
    float r = rsqrtf(ss * (1.f / 64.f) + EPS_);
    e0 *= r; e1 *= r;
    float inv = (float)exp(-((double)lane / 32.0) * 9.210340371976184);
    float f = (float)s * inv;
    float c  = (float)cos((double)f);
    float sn = (float)sin((double)f);
    float o0 =  e0 * c + e1 * sn;
    float o1 = -e0 * sn + e1 * c;
    if (isq) {
        float g = gain[h] * 0.125f;
        split_store(o0 * g, g_qhi, g_qlo, (size_t)s * D_ + h * HD_ + lane);
        split_store(o1 * g, g_qhi, g_qlo, (size_t)s * D_ + h * HD_ + lane + 32);
    } else {
        split_store(o0, g_khi, g_klo, (size_t)s * KVD_ + h * HD_ + lane);
        split_store(o1, g_khi, g_klo, (size_t)s * KVD_ + h * HD_ + lane + 32);
    }
}

// ---------------- V transpose ----------------
__global__ void vtrans_kernel()
{
    __shared__ float t[32][33];
    int s0 = blockIdx.x * 32, c0 = blockIdx.y * 32;
    int tx = threadIdx.x, ty = threadIdx.y;
    #pragma unroll
    for (int k = 0; k < 32; k += 8)
        t[ty + k][tx] = g_qkv[(size_t)(s0 + ty + k) * QKVD_ + 1280 + c0 + tx];
    __syncthreads();
    #pragma unroll
    for (int k = 0; k < 32; k += 8) {
        float v = t[tx][ty + k];
        split_store(v, g_vthi, g_vtlo, (size_t)(c0 + ty + k) * S_ + s0 + tx);
    }
}

// ---------------- fused flash attention: 128-row Q tiles, fp16 output ----------------
#define FA_DSM (32768 + 2 * 32768 + 1024)

__global__ __launch_bounds__(256, 1) void flash_kernel()
{
    int bi = 7 - (int)blockIdx.x;
    int h = blockIdx.y, kvh = h >> 2;
    extern __shared__ char fsm[];
    u32 base = (smem_u32(fsm) + 1023u) & ~1023u;

    int tid = threadIdx.x, lane = tid & 31, w = tid >> 5;
    int tig = lane & 3, grp = lane >> 2;

    for (int id = tid; id < 1024; id += 256) {
        int r = id >> 3, ck = id & 7;
        u32 so = sw128((u32)(r * 128 + ck * 16));
        size_t gq = (size_t)(bi * 128 + r) * D_ + h * HD_ + ck * 8;
        cpasync16(base + so, g_qhi + gq);
        cpasync16(base + 16384 + so, g_qlo + gq);
    }
    asm volatile("cp.async.commit_group;");

    #define FA_LOAD(st, jt) do { \
        u32 sb_ = base + 32768 + (u32)(st) * 32768; \
        for (int id_ = tid; id_ < 512; id_ += 256) { \
            int r_ = id_ >> 3, ck_ = id_ & 7; \
            u32 so_ = sw128((u32)(r_ * 128 + ck_ * 16)); \
            size_t gk_ = (size_t)((jt) * 64 + r_) * KVD_ + kvh * HD_ + ck_ * 8; \
            cpasync16(sb_ + so_,         g_khi + gk_); \
            cpasync16(sb_ + 8192 + so_,  g_klo + gk_); \
            size_t gv_ = (size_t)(kvh * 64 + r_) * S_ + (jt) * 64 + ck_ * 8; \
            cpasync16(sb_ + 16384 + so_, g_vthi + gv_); \
            cpasync16(sb_ + 24576 + so_, g_vtlo + gv_); \
        } \
        asm volatile("cp.async.commit_group;"); \
    } while (0)

    int n = 2 * bi + 2;
    FA_LOAD(0, 0);

    asm volatile("cp.async.wait_group 1;");
    __syncthreads();
    u32 qh[4][4], ql[4][4];
    #pragma unroll
    for (int kc = 0; kc < 4; kc++) {
        int lr = w * 16 + (lane & 15);
        int ch = kc * 2 + (lane >> 4);
        u32 so = sw128((u32)(lr * 128 + ch * 16));
        ldm_x4(qh[kc][0], qh[kc][1], qh[kc][2], qh[kc][3], base + so);
        ldm_x4(ql[kc][0], ql[kc][1], ql[kc][2], ql[kc][3], base + 16384 + so);
    }

    float o[8][4];
    #pragma unroll
    for (int nd = 0; nd < 8; nd++) { o[nd][0]=0.f; o[nd][1]=0.f; o[nd][2]=0.f; o[nd][3]=0.f; }
    float m0 = -1e30f, m1 = -1e30f, l0 = 0.f, l1 = 0.f;

    for (int jt = 0; jt < n; jt++) {
        if (jt + 1 < n) {
            FA_LOAD((jt + 1) & 1, jt + 1);
            asm volatile("cp.async.wait_group 1;");
        } else {
            asm volatile("cp.async.wait_group 0;");
        }
        __syncthreads();

        u32 kb = base + 32768 + (u32)(jt & 1) * 32768;

        float s[8][4];
        #pragma unroll
        for (int ni = 0; ni < 8; ni++) { s[ni][0]=0.f; s[ni][1]=0.f; s[ni][2]=0.f; s[ni][3]=0.f; }
        #pragma unroll
        for (int kc = 0; kc < 4; kc++) {
            u32 bh[8][2], bl[8][2];
            #pragma unroll
            for (int nj = 0; nj < 4; nj++) {
                int g = lane >> 3;
                int lr = nj * 16 + (((g >> 1) & 1) << 3) + (lane & 7);
                int ch = kc * 2 + (g & 1);
                u32 so = sw128((u32)(lr * 128 + ch * 16));
                u32 r0, r1, r2, r3;
                ldm_x4(r0, r1, r2, r3, kb + so);
                bh[nj * 2][0] = r0; bh[nj * 2][1] = r1;
                bh[nj * 2 + 1][0] = r2; bh[nj * 2 + 1][1] = r3;
                ldm_x4(r0, r1, r2, r3, kb + 8192 + so);
                bl[nj * 2][0] = r0; bl[nj * 2][1] = r1;
                bl[nj * 2 + 1][0] = r2; bl[nj * 2 + 1][1] = r3;
            }
            #pragma unroll
            for (int ni = 0; ni < 8; ni++) {
                mma16816(s[ni], qh[kc], bh[ni]);
                mma16816(s[ni], qh[kc], bl[ni]);
                mma16816(s[ni], ql[kc], bh[ni]);
            }
        }

        if (jt >= 2 * bi) {
            int ci0 = bi * 128 + w * 16 + grp, ci1 = ci0 + 8;
            #pragma unroll
            for (int ni = 0; ni < 8; ni++) {
                int cj = jt * 64 + ni * 8 + tig * 2;
                if (cj     > ci0) s[ni][0] = -1e30f;
                if (cj + 1 > ci0) s[ni][1] = -1e30f;
                if (cj     > ci1) s[ni][2] = -1e30f;
                if (cj + 1 > ci1) s[ni][3] = -1e30f;
            }
        }

        float tm0 = -1e30f, tm1 = -1e30f;
        #pragma unroll
        for (int ni = 0; ni < 8; ni++) {
            tm0 = fmaxf(tm0, fmaxf(s[ni][0], s[ni][1]));
            tm1 = fmaxf(tm1, fmaxf(s[ni][2], s[ni][3]));
        }
        tm0 = fmaxf(tm0, __shfl_xor_sync(0xffffffffu, tm0, 1));
        tm0 = fmaxf(tm0, __shfl_xor_sync(0xffffffffu, tm0, 2));
        tm1 = fmaxf(tm1, __shfl_xor_sync(0xffffffffu, tm1, 1));
        tm1 = fmaxf(tm1, __shfl_xor_sync(0xffffffffu, tm1, 2));
        float mn0 = fmaxf(m0, tm0), mn1 = fmaxf(m1, tm1);
        float a0 = expf(m0 - mn0), a1 = expf(m1 - mn1);
        m0 = mn0; m1 = mn1;

        float rs0 = 0.f, rs1 = 0.f;
        #pragma unroll
        for (int ni = 0; ni < 8; ni++) {
            s[ni][0] = expf(s[ni][0] - mn0);
            s[ni][1] = expf(s[ni][1] - mn0);
            s[ni][2] = expf(s[ni][2] - mn1);
            s[ni][3] = expf(s[ni][3] - mn1);
            rs0 += s[ni][0] + s[ni][1];
            rs1 += s[ni][2] + s[ni][3];
        }
        rs0 += __shfl_xor_sync(0xffffffffu, rs0, 1);
        rs0 += __shfl_xor_sync(0xffffffffu, rs0, 2);
        rs1 += __shfl_xor_sync(0xffffffffu, rs1, 1);
        rs1 += __shfl_xor_sync(0xffffffffu, rs1, 2);
        l0 = l0 * a0 + rs0;
        l1 = l1 * a1 + rs1;
        #pragma unroll
        for (int nd = 0; nd < 8; nd++) {
            o[nd][0] *= a0; o[nd][1] *= a0;
            o[nd][2] *= a1; o[nd][3] *= a1;
        }

        u32 vbh = kb + 16384, vbl = kb + 24576;
        #pragma unroll
        for (int kc = 0; kc < 4; kc++) {
            u32 pah[4], pal[4];
            split2(s[2 * kc][0],     s[2 * kc][1],     pah[0], pal[0]);
            split2(s[2 * kc][2],     s[2 * kc][3],     pah[1], pal[1]);
            split2(s[2 * kc + 1][0], s[2 * kc + 1][1], pah[2], pal[2]);
            split2(s[2 * kc + 1][2], s[2 * kc + 1][3], pah[3], pal[3]);
            u32 vh[8][2], vl[8][2];
            #pragma unroll
            for (int nj = 0; nj < 4; nj++) {
                int g = lane >> 3;
                int lr = nj * 16 + (((g >> 1) & 1) << 3) + (lane & 7);
                int ch = kc * 2 + (g & 1);
                u32 so = sw128((u32)(lr * 128 + ch * 16));
                u32 r0, r1, r2, r3;
                ldm_x4(r0, r1, r2, r3, vbh + so);
                vh[nj * 2][0] = r0; vh[nj * 2][1] = r1;
                vh[nj * 2 + 1][0] = r2; vh[nj * 2 + 1][1] = r3;
                ldm_x4(r0, r1, r2, r3, vbl + so);
                vl[nj * 2][0] = r0; vl[nj * 2][1] = r1;
                vl[nj * 2 + 1][0] = r2; vl[nj * 2 + 1][1] = r3;
            }
            #pragma unroll
            for (int nd = 0; nd < 8; nd++) {
                mma16816(o[nd], pah, vh[nd]);
                mma16816(o[nd], pah, vl[nd]);
                mma16816(o[nd], pal, vh[nd]);
            }
        }
        __syncthreads();
    }

    float inv0 = 1.0f / l0, inv1 = 1.0f / l1;
    int gi0 = bi * 128 + w * 16 + grp;
    #pragma unroll
    for (int nd = 0; nd < 8; nd++) {
        int gd = h * HD_ + nd * 8 + tig * 2;
        g_a16[(size_t)gi0 * D_ + gd]           = __float2half_rn(o[nd][0] * inv0);
        g_a16[(size_t)gi0 * D_ + gd + 1]       = __float2half_rn(o[nd][1] * inv0);
        g_a16[(size_t)(gi0 + 8) * D_ + gd]     = __float2half_rn(o[nd][2] * inv1);
        g_a16[(size_t)(gi0 + 8) * D_ + gd + 1] = __float2half_rn(o[nd][3] * inv1);
    }
    #undef FA_LOAD
}

// ---------------- shared GEMM pieces (fp16 single plane) ----------------
template<int BM, int BN>
__device__ __forceinline__ void load_stage16(
    const __half* A, const __half* Bq,
    u32 sbase, int row0, int col0, int K, int k0, int tid)
{
    for (int id = tid; id < BM * 8; id += 256) {
        int r = id >> 3, ck = id & 7;
        u32 so = sw128((u32)(r * 128 + ck * 16));
        cpasync16(sbase + so, A + (size_t)(row0 + r) * K + k0 + ck * 8);
    }
    for (int id = tid; id < BN * 8; id += 256) {
        int r = id >> 3, ck = id & 7;
        u32 so = sw128((u32)(r * 128 + ck * 16));
        cpasync16(sbase + (u32)BM * 128 + so, Bq + (size_t)(col0 + r) * K + k0 + ck * 8);
    }
    asm volatile("cp.async.commit_group;");
}

// EPI: 0 = write g_qkv (fp32), 1 = residual add into g_x, 2 = relu^2 -> g_f16, 3 = Cout
template<int EPI>
__device__ __forceinline__ void epi_store(float v, int gr, int c, float* Cout, int ldc)
{
    if (EPI == 0) {
        g_qkv[(size_t)gr * QKVD_ + c] = v;
    } else if (EPI == 1) {
        g_x[(size_t)gr * D_ + c] += v;
    } else if (EPI == 2) {
        float t = fmaxf(v, 0.f);
        g_f16[(size_t)gr * FF_ + c] = __float2half_rn(t * t);
    } else {
        Cout[(size_t)gr * ldc + c] = v;
    }
}

// ---------------- small GEMM: 128x64, 2-stage, 2 CTAs/SM, fp16 ----------------
template<int EPI, int WSEL, int ASEL>
__global__ __launch_bounds__(256, 2)
void qgemm2_kernel(float* __restrict__ Cout, int layer, int N, int K, int ldc)
{
    constexpr int BM = 128, BN = 64;
    constexpr int MI = 2, NI = 4;
    constexpr u32 STB = (u32)(BM + BN) * 128;    // 24576

    extern __shared__ char dsm[];
    u32 base = (smem_u32(dsm) + 1023u) & ~1023u;

    int tid = threadIdx.x, lane = tid & 31, wid = tid >> 5;
    int wm = wid % 4, wn = wid / 4;
    int row0 = blockIdx.y * BM, col0 = blockIdx.x * BN;

    const __half* A  = a16sel<ASEL>();
    const __half* Bq = qsel<WSEL>() + (size_t)layer * N * K;
    const float* Sc = scsel<WSEL>() + (size_t)layer * N;

    float acc[MI][NI][4];
    #pragma unroll
    for (int mi = 0; mi < MI; mi++)
        #pragma unroll
        for (int ni = 0; ni < NI; ni++) {
            acc[mi][ni][0] = 0.f; acc[mi][ni][1] = 0.f;
            acc[mi][ni][2] = 0.f; acc[mi][ni][3] = 0.f;
        }

    int n = K >> 6;
    load_stage16<BM, BN>(A, Bq, base,       row0, col0, K, 0,  tid);
    load_stage16<BM, BN>(A, Bq, base + STB, row0, col0, K, 64, tid);

    for (int it = 0; it < n; it++) {
        if (it + 1 < n) { asm volatile("cp.async.wait_group 1;"); }
        else            { asm volatile("cp.async.wait_group 0;"); }
        __syncthreads();

        u32 sb = base + (u32)(it & 1) * STB;
        #pragma unroll
        for (int kc = 0; kc < 4; kc++) {
            u32 ah[MI][4];
            #pragma unroll
            for (int mi = 0; mi < MI; mi++) {
                int lr = wm * 32 + mi * 16 + (lane & 15);
                int ch = kc * 2 + (lane >> 4);
                u32 so = sw128((u32)(lr * 128 + ch * 16));
                ldm_x4(ah[mi][0], ah[mi][1], ah[mi][2], ah[mi][3], sb + so);
            }
            u32 bb[NI][2];
            #pragma unroll
            for (int nj = 0; nj < NI / 2; nj++) {
                int g = lane >> 3;
                int lr = wn * 32 + nj * 16 + (((g >> 1) & 1) << 3) + (lane & 7);
                int ch = kc * 2 + (g & 1);
                u32 r0, r1, r2, r3;
                ldm_x4(r0, r1, r2, r3, sb + (u32)BM * 128 + sw128((u32)(lr * 128 + ch * 16)));
                bb[nj * 2][0] = r0; bb[nj * 2][1] = r1;
                bb[nj * 2 + 1][0] = r2; bb[nj * 2 + 1][1] = r3;
            }
            #pragma unroll
            for (int mi = 0; mi < MI; mi++)
                #pragma unroll
                for (int ni = 0; ni < NI; ni++)
                    mma16816h(acc[mi][ni], ah[mi], bb[ni]);
        }
        __syncthreads();
        if (it + 2 < n)
            load_stage16<BM, BN>(A, Bq, base + (u32)(it & 1) * STB,
                                 row0, col0, K, (it + 2) << 6, tid);
    }

    #pragma unroll
    for (int mi = 0; mi < MI; mi++) {
        #pragma unroll
        for (int ni = 0; ni < NI; ni++) {
            int gr0 = row0 + wm * 32 + mi * 16 + (lane >> 2);
            int gc  = col0 + wn * 32 + ni * 8 + ((lane & 3) << 1);
            #pragma unroll
            for (int half = 0; half < 2; half++) {
                int gr = gr0 + half * 8;
                #pragma unroll
                for (int e = 0; e < 2; e++) {
                    int c = gc + e;
                    if (c >= N) continue;
                    epi_store<EPI>(acc[mi][ni][half * 2 + e] * Sc[c], gr, c, Cout, ldc);
                }
            }
        }
    }
}

// ---------------- big GEMM: 128x128, 3-stage, fp16 ----------------
template<int EPI, int WSEL, int ASEL>
__global__ __launch_bounds__(256, 1)
void qgemm3_kernel(float* __restrict__ Cout, int layer, int N, int K, int ldc)
{
    constexpr int BM = 128, BN = 128;
    constexpr int MI = 4, NI = 4;
    constexpr u32 STB = (u32)(BM + BN) * 128;    // 32768

    extern __shared__ char dsm[];
    u32 base = (smem_u32(dsm) + 1023u) & ~1023u;

    int tid = threadIdx.x, lane = tid & 31, wid = tid >> 5;
    int wm = wid % 2, wn = wid / 2;
    int row0 = blockIdx.y * BM, col0 = blockIdx.x * BN;

    const __half* A  = a16sel<ASEL>();
    const __half* Bq = qsel<WSEL>() + (size_t)layer * N * K;
    const float* Sc = scsel<WSEL>() + (size_t)layer * N;

    float acc[MI][NI][4];
    #pragma unroll
    for (int mi = 0; mi < MI; mi++)
        #pragma unroll
        for (int ni = 0; ni < NI; ni++) {
            acc[mi][ni][0] = 0.f; acc[mi][ni][1] = 0.f;
            acc[mi][ni][2] = 0.f; acc[mi][ni][3] = 0.f;
        }

    int n = K >> 6;
    load_stage16<BM, BN>(A, Bq, base,       row0, col0, K, 0,  tid);
    load_stage16<BM, BN>(A, Bq, base + STB, row0, col0, K, 64, tid);

    for (int it = 0; it < n; it++) {
        asm volatile("cp.async.wait_group 1;");
        __syncthreads();

        int ldst = it + 2;
        if (ldst < n) {
            load_stage16<BM, BN>(A, Bq, base + (u32)(ldst % 3) * STB,
                                 row0, col0, K, ldst << 6, tid);
        } else {
            asm volatile("cp.async.commit_group;");
        }

        u32 sb = base + (u32)(it % 3) * STB;
        #pragma unroll
        for (int kc = 0; kc < 4; kc++) {
            u32 ah[MI][4];
            #pragma unroll
            for (int mi = 0; mi < MI; mi++) {
                int lr = wm * 64 + mi * 16 + (lane & 15);
                int ch = kc * 2 + (lane >> 4);
                u32 so = sw128((u32)(lr * 128 + ch * 16));
                ldm_x4(ah[mi][0], ah[mi][1], ah[mi][2], ah[mi][3], sb + so);
            }
            u32 bb[NI][2];
            #pragma unroll
            for (int nj = 0; nj < NI / 2; nj++) {
                int g = lane >> 3;
                int lr = wn * 32 + nj * 16 + (((g >> 1) & 1) << 3) + (lane & 7);
                int ch = kc * 2 + (g & 1);
                u32 r0, r1, r2, r3;
                ldm_x4(r0, r1, r2, r3, sb + (u32)BM * 128 + sw128((u32)(lr * 128 + ch * 16)));
                bb[nj * 2][0] = r0; bb[nj * 2][1] = r1;
                bb[nj * 2 + 1][0] = r2; bb[nj * 2 + 1][1] = r3;
            }
            #pragma unroll
            for (int mi = 0; mi < MI; mi++)
                #pragma unroll
                for (int ni = 0; ni < NI; ni++)
                    mma16816h(acc[mi][ni], ah[mi], bb[ni]);
        }
    }

    #pragma unroll
    for (int mi = 0; mi < MI; mi++) {
        #pragma unroll
        for (int ni = 0; ni < NI; ni++) {
            int gr0 = row0 + wm * 64 + mi * 16 + (lane >> 2);
            int gc  = col0 + wn * 32 + ni * 8 + ((lane & 3) << 1);
            #pragma unroll
            for (int half = 0; half < 2; half++) {
                int gr = gr0 + half * 8;
                #pragma unroll
                for (int e = 0; e < 2; e++) {
                    int c = gc + e;
                    if (c >= N) continue;
                    epi_store<EPI>(acc[mi][ni][half * 2 + e] * Sc[c], gr, c, Cout, ldc);
                }
            }
        }
    }
}

#define DSM_SMALL (2 * (128 + 64)  * 128 + 1024)
#define DSM_BIG   (3 * (128 + 128) * 128 + 1024)

// ---------------- host orchestration ----------------
extern "C" void kernel_launch(void* const* d_in, const int* in_sizes, int n_in,
                              void* d_out, int out_size)
{
    (void)in_sizes; (void)n_in; (void)out_size;
    const int*   idx = (const int*)  d_in[0];
    const float* emb = (const float*)d_in[1];
    const float* wq  = (const float*)d_in[2];
    const float* wk  = (const float*)d_in[3];
    const float* wv  = (const float*)d_in[4];
    const float* wo  = (const float*)d_in[5];
    const float* qg  = (const float*)d_in[6];
    const float* wfc = (const float*)d_in[7];
    const float* wpr = (const float*)d_in[8];
    const float* lm  = (const float*)d_in[9];
    float* out = (float*)d_out;

    cudaFuncSetAttribute(qgemm2_kernel<0, 0, 0>,
                         cudaFuncAttributeMaxDynamicSharedMemorySize, DSM_SMALL);
    cudaFuncSetAttribute(qgemm2_kernel<1, 1, 1>,
                         cudaFuncAttributeMaxDynamicSharedMemorySize, DSM_SMALL);
    cudaFuncSetAttribute(qgemm2_kernel<1, 3, 2>,
                         cudaFuncAttributeMaxDynamicSharedMemorySize, DSM_SMALL);
    cudaFuncSetAttribute(qgemm3_kernel<2, 2, 0>,
                         cudaFuncAttributeMaxDynamicSharedMemorySize, DSM_BIG);
    cudaFuncSetAttribute(qgemm3_kernel<3, 4, 0>,
                         cudaFuncAttributeMaxDynamicSharedMemorySize, DSM_BIG);
    cudaFuncSetAttribute(flash_kernel,
                         cudaFuncAttributeMaxDynamicSharedMemorySize, FA_DSM);

    quant_kernel<0, 4><<<L_ * D_,    256>>>(wq,  D_,   QKVD_, 0);
    quant_kernel<0, 4><<<L_ * KVD_,  256>>>(wk,  KVD_, QKVD_, 1024);
    quant_kernel<0, 4><<<L_ * KVD_,  256>>>(wv,  KVD_, QKVD_, 1280);
    quant_kernel<1, 4><<<L_ * D_,    256>>>(wo,  L_ * D_,  0, 0);
    quant_kernel<2, 4><<<L_ * FF_,   256>>>(wfc, L_ * FF_, 0, 0);
    quant_kernel<3, 16><<<L_ * D_,   256>>>(wpr, L_ * D_,  0, 0);
    quant_kernel<4, 4><<<V_,         256>>>(lm,  V_,       0, 0);

    embed_kernel<<<(S_ * D_) / 256, 256>>>(idx, emb);

    for (int l = 0; l < L_; l++) {
        rmsnorm_h_kernel<<<S_, 256>>>();

        qgemm2_kernel<0, 0, 0><<<dim3(QKVD_ / 64, S_ / 128), 256, DSM_SMALL>>>(
            nullptr, l, QKVD_, D_, QKVD_);

        qkpost_kernel<<<(S_ * 20) / 4, 128>>>(qg + l * H_);
        vtrans_kernel<<<dim3(S_ / 32, KVD_ / 32), dim3(32, 8)>>>();

        flash_kernel<<<dim3(8, H_), 256, FA_DSM>>>();

        qgemm2_kernel<1, 1, 1><<<dim3(D_ / 64, S_ / 128), 256, DSM_SMALL>>>(
            nullptr, l, D_, D_, D_);

        rmsnorm_h_kernel<<<S_, 256>>>();

        qgemm3_kernel<2, 2, 0><<<dim3(FF_ / 128, S_ / 128), 256, DSM_BIG>>>(
            nullptr, l, FF_, D_, FF_);

        qgemm2_kernel<1, 3, 2><<<dim3(D_ / 64, S_ / 128), 256, DSM_SMALL>>>(
            nullptr, l, D_, FF_, D_);
    }

    rmsnorm_h_kernel<<<S_, 256>>>();
    qgemm3_kernel<3, 4, 0><<<dim3(VPAD_ / 128, S_ / 128), 256, DSM_BIG>>>(
        out, 0, V_, D_, V_);
}

// round 17
// speedup vs baseline: 1.3000x; 1.1107x over previous
#include <cuda_runtime.h>
#include <cuda_fp16.h>
#include <cuda_bf16.h>
#include <stdint.h>
#include <cstdint>
#include <math.h>
#include <float.h>

typedef unsigned int u32;

#define S_   1024
#define D_   1024
#define H_   16
#define KV_  4
#define HD_  64
#define KVD_ 256
#define FF_  4096
#define L_   8
#define V_   50257
#define VPAD_ 50304
#define QKVD_ 1536
#define EPS_ 1.1920928955078125e-07f

// ---------------- device globals ----------------
__device__ __half g_qw16  [L_ * QKVD_ * D_];
__device__ __half g_qwo16 [L_ * D_   * D_ ];
__device__ __half g_qwfc16[L_ * FF_  * D_ ];
__device__ __half g_qwpr16[L_ * D_   * FF_];
__device__ __half g_qlmh  [(size_t)VPAD_ * D_];
__device__ float g_sqkv[L_ * QKVD_];
__device__ float g_swo [L_ * D_ ];
__device__ float g_swfc[L_ * FF_];
__device__ float g_swpr[L_ * D_ ];
__device__ float g_slm [VPAD_];

__device__ float g_x  [S_ * D_ ];
__device__ __half g_h16[S_ * D_ ];
__device__ __half g_a16[S_ * D_ ];
__device__ __half g_f16[S_ * FF_];
__device__ float g_qkv[S_ * QKVD_];

__device__ __nv_bfloat16 g_qhi [S_ * D_ ];
__device__ __nv_bfloat16 g_qlo [S_ * D_ ];
__device__ __nv_bfloat16 g_khi [S_ * KVD_];
__device__ __nv_bfloat16 g_klo [S_ * KVD_];
__device__ __nv_bfloat16 g_vthi[KVD_ * S_];
__device__ __nv_bfloat16 g_vtlo[KVD_ * S_];

// ---------------- helpers ----------------
__device__ __forceinline__ u32 smem_u32(const void* p) {
    return (u32)__cvta_generic_to_shared(p);
}
__device__ __forceinline__ void cpasync16(u32 dst, const void* src) {
    asm volatile("cp.async.cg.shared.global [%0], [%1], 16;" :: "r"(dst), "l"(src));
}
__device__ __forceinline__ void ldm_x4(u32& r0, u32& r1, u32& r2, u32& r3, u32 a) {
    asm volatile("ldmatrix.sync.aligned.m8n8.x4.shared.b16 {%0,%1,%2,%3}, [%4];"
        : "=r"(r0), "=r"(r1), "=r"(r2), "=r"(r3) : "r"(a));
}
__device__ __forceinline__ void mma16816(float* d, const u32* a, const u32* b) {
    asm volatile("mma.sync.aligned.m16n8k16.row.col.f32.bf16.bf16.f32 "
        "{%0,%1,%2,%3}, {%4,%5,%6,%7}, {%8,%9}, {%0,%1,%2,%3};"
        : "+f"(d[0]), "+f"(d[1]), "+f"(d[2]), "+f"(d[3])
        : "r"(a[0]), "r"(a[1]), "r"(a[2]), "r"(a[3]), "r"(b[0]), "r"(b[1]));
}
__device__ __forceinline__ void mma16816h(float* d, const u32* a, const u32* b) {
    asm volatile("mma.sync.aligned.m16n8k16.row.col.f32.f16.f16.f32 "
        "{%0,%1,%2,%3}, {%4,%5,%6,%7}, {%8,%9}, {%0,%1,%2,%3};"
        : "+f"(d[0]), "+f"(d[1]), "+f"(d[2]), "+f"(d[3])
        : "r"(a[0]), "r"(a[1]), "r"(a[2]), "r"(a[3]), "r"(b[0]), "r"(b[1]));
}
__device__ __forceinline__ u32 sw128(u32 b) {
    return b ^ ((b >> 3) & 0x70u);
}
__device__ __forceinline__ void split_store(float v, __nv_bfloat16* hi, __nv_bfloat16* lo, size_t i) {
    __nv_bfloat16 h = __float2bfloat16(v);
    hi[i] = h;
    lo[i] = __float2bfloat16(v - __bfloat162float(h));
}
__device__ __forceinline__ void split2(float a, float b, u32& hi, u32& lo) {
    __nv_bfloat16 ha = __float2bfloat16(a), hb = __float2bfloat16(b);
    hi = (u32)__bfloat16_as_ushort(ha) | ((u32)__bfloat16_as_ushort(hb) << 16);
    lo = (u32)__bfloat16_as_ushort(__float2bfloat16(a - __bfloat162float(ha)))
       | ((u32)__bfloat16_as_ushort(__float2bfloat16(b - __bfloat162float(hb))) << 16);
}
__device__ __forceinline__ void max2_upd(float& m1, float& m2, float a) {
    float t = fminf(m1, a);
    m1 = fmaxf(m1, a);
    m2 = fmaxf(m2, t);
}

template<int W> __device__ __forceinline__ __half* qsel() {
    if (W == 0) return g_qw16;
    if (W == 1) return g_qwo16;
    if (W == 2) return g_qwfc16;
    if (W == 3) return g_qwpr16;
    return g_qlmh;
}
template<int W> __device__ __forceinline__ float* scsel() {
    if (W == 0) return g_sqkv;
    if (W == 1) return g_swo;
    if (W == 2) return g_swfc;
    if (W == 3) return g_swpr;
    return g_slm;
}
template<int A> __device__ __forceinline__ const __half* a16sel() {
    if (A == 0) return g_h16;
    if (A == 1) return g_a16;
    return g_f16;
}

// ---------------- fake-quant: warp-per-1024-segment, shfl reduction ----------------
// WPR warps per row (row length = WPR*1024). Block = 256 threads = 8 warps.
template<int WSEL, int WPR>
__global__ void quantw_kernel(const float* __restrict__ W, int nrows, int rpl, int ld, int off)
{
    const int n = WPR * 1024;
    int wid = threadIdx.x >> 5, lane = threadIdx.x & 31;
    const int RPB = 8 / WPR;
    int rl = wid / WPR;
    int seg = wid % WPR;
    int blk = blockIdx.x * RPB + rl;

    __shared__ float sm1[8], sm2[8];

    float4 v[8];
    float m1 = 0.f, m2 = 0.f;
    int valid = (blk < nrows);
    int l = 0, out_row = 0;
    const float4* w4 = nullptr;
    if (valid) {
        l = blk / rpl;
        out_row = l * ld + off + (blk % rpl);
        w4 = (const float4*)(W + (size_t)blk * n) + seg * 256;
        #pragma unroll
        for (int j = 0; j < 8; j++) {
            v[j] = w4[lane + j * 32];
            max2_upd(m1, m2, fabsf(v[j].x));
            max2_upd(m1, m2, fabsf(v[j].y));
            max2_upd(m1, m2, fabsf(v[j].z));
            max2_upd(m1, m2, fabsf(v[j].w));
        }
    }
    // warp shfl top-2 merge
    #pragma unroll
    for (int o = 16; o; o >>= 1) {
        float o1 = __shfl_xor_sync(0xffffffffu, m1, o);
        float o2 = __shfl_xor_sync(0xffffffffu, m2, o);
        float n2 = fmaxf(fmaxf(m2, o2), fminf(m1, o1));
        m1 = fmaxf(m1, o1);
        m2 = n2;
    }
    if (WPR > 1) {
        if (lane == 0) { sm1[wid] = m1; sm2[wid] = m2; }
        __syncthreads();
        float M1 = sm1[rl * WPR], M2 = sm2[rl * WPR];
        #pragma unroll
        for (int k = 1; k < WPR; k++) {
            float b1 = sm1[rl * WPR + k];
            float b2 = sm2[rl * WPR + k];
            float n2 = fmaxf(fmaxf(M2, b2), fminf(M1, b1));
            M1 = fmaxf(M1, b1);
            M2 = n2;
        }
        m1 = M1; m2 = M2;
    }
    if (!valid) return;

    float idxf = 0.9999984f * (float)(n - 1);
    float frac = idxf - (float)(n - 2);
    float clip = m2 * (1.0f - frac) + m1 * frac;
    float scale = fmaxf(__fdiv_rn(clip, 127.0f), 1.0f / 127.0f);
    if (seg == 0 && lane == 0)
        scsel<WSEL>()[out_row] = __half2float(__float2half_rn(scale));

    __half* qb = qsel<WSEL>() + (size_t)out_row * n + seg * 1024;
    #pragma unroll
    for (int j = 0; j < 8; j++) {
        float q[4];
        float* vv = (float*)&v[j];
        #pragma unroll
        for (int e = 0; e < 4; e++) {
            float c = fminf(fmaxf(vv[e], -clip), clip);
            float t = rintf(__fdiv_rn(c, scale));
            q[e] = fminf(fmaxf(t, -127.f), 127.f);
        }
        __half2 lo2 = __floats2half2_rn(q[0], q[1]);
        __half2 hi2 = __floats2half2_rn(q[2], q[3]);
        uint2 pk;
        pk.x = *(u32*)&lo2;
        pk.y = *(u32*)&hi2;
        ((uint2*)qb)[lane + j * 32] = pk;
    }
}

// ---------------- embedding ----------------
__global__ void embed_kernel(const int* __restrict__ idx, const float* __restrict__ emb)
{
    int i = blockIdx.x * blockDim.x + threadIdx.x;
    int s = i >> 10, d = i & 1023;
    g_x[i] = emb[(size_t)idx[s] * D_ + d];
}

// ---------------- rmsnorm -> fp16 single ----------------
__global__ void rmsnorm_h_kernel()
{
    int row = blockIdx.x;
    const float* xr = g_x + (size_t)row * D_;
    int tid = threadIdx.x;
    float ss = 0.f;
    for (int i = tid; i < D_; i += 256) { float v = xr[i]; ss += v * v; }
    __shared__ float sh[256];
    sh[tid] = ss; __syncthreads();
    for (int o = 128; o; o >>= 1) {
        if (tid < o) sh[tid] += sh[tid + o];
        __syncthreads();
    }
    float r = rsqrtf(sh[0] / (float)D_ + EPS_);
    for (int i = tid; i < D_; i += 256) {
        g_h16[(size_t)row * D_ + i] = __float2half_rn(xr[i] * r);
    }
}

// ---------------- merged per-head RMS + RoPE + gain (bf16 hi/lo for flash) ----------------
__global__ void qkpost_kernel(const float* __restrict__ gain)
{
    int warp = (blockIdx.x * blockDim.x + threadIdx.x) >> 5;
    int lane = threadIdx.x & 31;
    int s = warp / 20, j = warp % 20;
    if (s >= S_) return;
    int isq = (j < 16);
    int h = isq ? j : j - 16;
    int off = isq ? 0 : 1024;
    const float* base = g_qkv + (size_t)s * QKVD_ + off + h * HD_;
    float e0 = base[lane], e1 = base[lane + 32];
    float ss = e0 * e0 + e1 * e1;
    #pragma unroll
    for (int o = 16; o; o >>= 1) ss += __shfl_xor_sync(0xffffffffu, ss, o);
    float r = rsqrtf(ss * (1.f / 64.f) + EPS_);
    e0 *= r; e1 *= r;
    float inv = (float)exp(-((double)lane / 32.0) * 9.210340371976184);
    float f = (float)s * inv;
    float c  = (float)cos((double)f);
    float sn = (float)sin((double)f);
    float o0 =  e0 * c + e1 * sn;
    float o1 = -e0 * sn + e1 * c;
    if (isq) {
        float g = gain[h] * 0.125f;
        split_store(o0 * g, g_qhi, g_qlo, (size_t)s * D_ + h * HD_ + lane);
        split_store(o1 * g, g_qhi, g_qlo, (size_t)s * D_ + h * HD_ + lane + 32);
    } else {
        split_store(o0, g_khi, g_klo, (size_t)s * KVD_ + h * HD_ + lane);
        split_store(o1, g_khi, g_klo, (size_t)s * KVD_ + h * HD_ + lane + 32);
    }
}

// ---------------- V transpose ----------------
__global__ void vtrans_kernel()
{
    __shared__ float t[32][33];
    int s0 = blockIdx.x * 32, c0 = blockIdx.y * 32;
    int tx = threadIdx.x, ty = threadIdx.y;
    #pragma unroll
    for (int k = 0; k < 32; k += 8)
        t[ty + k][tx] = g_qkv[(size_t)(s0 + ty + k) * QKVD_ + 1280 + c0 + tx];
    __syncthreads();
    #pragma unroll
    for (int k = 0; k < 32; k += 8) {
        float v = t[tx][ty + k];
        split_store(v, g_vthi, g_vtlo, (size_t)(c0 + ty + k) * S_ + s0 + tx);
    }
}

// ---------------- fused flash attention: 128-row Q tiles, fp16 output ----------------
#define FA_DSM (32768 + 2 * 32768 + 1024)

__global__ __launch_bounds__(256, 1) void flash_kernel()
{
    int bi = 7 - (int)blockIdx.x;
    int h = blockIdx.y, kvh = h >> 2;
    extern __shared__ char fsm[];
    u32 base = (smem_u32(fsm) + 1023u) & ~1023u;

    int tid = threadIdx.x, lane = tid & 31, w = tid >> 5;
    int tig = lane & 3, grp = lane >> 2;

    for (int id = tid; id < 1024; id += 256) {
        int r = id >> 3, ck = id & 7;
        u32 so = sw128((u32)(r * 128 + ck * 16));
        size_t gq = (size_t)(bi * 128 + r) * D_ + h * HD_ + ck * 8;
        cpasync16(base + so, g_qhi + gq);
        cpasync16(base + 16384 + so, g_qlo + gq);
    }
    asm volatile("cp.async.commit_group;");

    #define FA_LOAD(st, jt) do { \
        u32 sb_ = base + 32768 + (u32)(st) * 32768; \
        for (int id_ = tid; id_ < 512; id_ += 256) { \
            int r_ = id_ >> 3, ck_ = id_ & 7; \
            u32 so_ = sw128((u32)(r_ * 128 + ck_ * 16)); \
            size_t gk_ = (size_t)((jt) * 64 + r_) * KVD_ + kvh * HD_ + ck_ * 8; \
            cpasync16(sb_ + so_,         g_khi + gk_); \
            cpasync16(sb_ + 8192 + so_,  g_klo + gk_); \
            size_t gv_ = (size_t)(kvh * 64 + r_) * S_ + (jt) * 64 + ck_ * 8; \
            cpasync16(sb_ + 16384 + so_, g_vthi + gv_); \
            cpasync16(sb_ + 24576 + so_, g_vtlo + gv_); \
        } \
        asm volatile("cp.async.commit_group;"); \
    } while (0)

    int n = 2 * bi + 2;
    FA_LOAD(0, 0);

    asm volatile("cp.async.wait_group 1;");
    __syncthreads();
    u32 qh[4][4], ql[4][4];
    #pragma unroll
    for (int kc = 0; kc < 4; kc++) {
        int lr = w * 16 + (lane & 15);
        int ch = kc * 2 + (lane >> 4);
        u32 so = sw128((u32)(lr * 128 + ch * 16));
        ldm_x4(qh[kc][0], qh[kc][1], qh[kc][2], qh[kc][3], base + so);
        ldm_x4(ql[kc][0], ql[kc][1], ql[kc][2], ql[kc][3], base + 16384 + so);
    }

    float o[8][4];
    #pragma unroll
    for (int nd = 0; nd < 8; nd++) { o[nd][0]=0.f; o[nd][1]=0.f; o[nd][2]=0.f; o[nd][3]=0.f; }
    float m0 = -1e30f, m1 = -1e30f, l0 = 0.f, l1 = 0.f;

    for (int jt = 0; jt < n; jt++) {
        if (jt + 1 < n) {
            FA_LOAD((jt + 1) & 1, jt + 1);
            asm volatile("cp.async.wait_group 1;");
        } else {
            asm volatile("cp.async.wait_group 0;");
        }
        __syncthreads();

        u32 kb = base + 32768 + (u32)(jt & 1) * 32768;

        float s[8][4];
        #pragma unroll
        for (int ni = 0; ni < 8; ni++) { s[ni][0]=0.f; s[ni][1]=0.f; s[ni][2]=0.f; s[ni][3]=0.f; }
        #pragma unroll
        for (int kc = 0; kc < 4; kc++) {
            u32 bh[8][2], bl[8][2];
            #pragma unroll
            for (int nj = 0; nj < 4; nj++) {
                int g = lane >> 3;
                int lr = nj * 16 + (((g >> 1) & 1) << 3) + (lane & 7);
                int ch = kc * 2 + (g & 1);
                u32 so = sw128((u32)(lr * 128 + ch * 16));
                u32 r0, r1, r2, r3;
                ldm_x4(r0, r1, r2, r3, kb + so);
                bh[nj * 2][0] = r0; bh[nj * 2][1] = r1;
                bh[nj * 2 + 1][0] = r2; bh[nj * 2 + 1][1] = r3;
                ldm_x4(r0, r1, r2, r3, kb + 8192 + so);
                bl[nj * 2][0] = r0; bl[nj * 2][1] = r1;
                bl[nj * 2 + 1][0] = r2; bl[nj * 2 + 1][1] = r3;
            }
            #pragma unroll
            for (int ni = 0; ni < 8; ni++) {
                mma16816(s[ni], qh[kc], bh[ni]);
                mma16816(s[ni], qh[kc], bl[ni]);
                mma16816(s[ni], ql[kc], bh[ni]);
            }
        }

        if (jt >= 2 * bi) {
            int ci0 = bi * 128 + w * 16 + grp, ci1 = ci0 + 8;
            #pragma unroll
            for (int ni = 0; ni < 8; ni++) {
                int cj = jt * 64 + ni * 8 + tig * 2;
                if (cj     > ci0) s[ni][0] = -1e30f;
                if (cj + 1 > ci0) s[ni][1] = -1e30f;
                if (cj     > ci1) s[ni][2] = -1e30f;
                if (cj + 1 > ci1) s[ni][3] = -1e30f;
            }
        }

        float tm0 = -1e30f, tm1 = -1e30f;
        #pragma unroll
        for (int ni = 0; ni < 8; ni++) {
            tm0 = fmaxf(tm0, fmaxf(s[ni][0], s[ni][1]));
            tm1 = fmaxf(tm1, fmaxf(s[ni][2], s[ni][3]));
        }
        tm0 = fmaxf(tm0, __shfl_xor_sync(0xffffffffu, tm0, 1));
        tm0 = fmaxf(tm0, __shfl_xor_sync(0xffffffffu, tm0, 2));
        tm1 = fmaxf(tm1, __shfl_xor_sync(0xffffffffu, tm1, 1));
        tm1 = fmaxf(tm1, __shfl_xor_sync(0xffffffffu, tm1, 2));
        float mn0 = fmaxf(m0, tm0), mn1 = fmaxf(m1, tm1);
        float a0 = expf(m0 - mn0), a1 = expf(m1 - mn1);
        m0 = mn0; m1 = mn1;

        float rs0 = 0.f, rs1 = 0.f;
        #pragma unroll
        for (int ni = 0; ni < 8; ni++) {
            s[ni][0] = expf(s[ni][0] - mn0);
            s[ni][1] = expf(s[ni][1] - mn0);
            s[ni][2] = expf(s[ni][2] - mn1);
            s[ni][3] = expf(s[ni][3] - mn1);
            rs0 += s[ni][0] + s[ni][1];
            rs1 += s[ni][2] + s[ni][3];
        }
        rs0 += __shfl_xor_sync(0xffffffffu, rs0, 1);
        rs0 += __shfl_xor_sync(0xffffffffu, rs0, 2);
        rs1 += __shfl_xor_sync(0xffffffffu, rs1, 1);
        rs1 += __shfl_xor_sync(0xffffffffu, rs1, 2);
        l0 = l0 * a0 + rs0;
        l1 = l1 * a1 + rs1;
        #pragma unroll
        for (int nd = 0; nd < 8; nd++) {
            o[nd][0] *= a0; o[nd][1] *= a0;
            o[nd][2] *= a1; o[nd][3] *= a1;
        }

        u32 vbh = kb + 16384, vbl = kb + 24576;
        #pragma unroll
        for (int kc = 0; kc < 4; kc++) {
            u32 pah[4], pal[4];
            split2(s[2 * kc][0],     s[2 * kc][1],     pah[0], pal[0]);
            split2(s[2 * kc][2],     s[2 * kc][3],     pah[1], pal[1]);
            split2(s[2 * kc + 1][0], s[2 * kc + 1][1], pah[2], pal[2]);
            split2(s[2 * kc + 1][2], s[2 * kc + 1][3], pah[3], pal[3]);
            u32 vh[8][2], vl[8][2];
            #pragma unroll
            for (int nj = 0; nj < 4; nj++) {
                int g = lane >> 3;
                int lr = nj * 16 + (((g >> 1) & 1) << 3) + (lane & 7);
                int ch = kc * 2 + (g & 1);
                u32 so = sw128((u32)(lr * 128 + ch * 16));
                u32 r0, r1, r2, r3;
                ldm_x4(r0, r1, r2, r3, vbh + so);
                vh[nj * 2][0] = r0; vh[nj * 2][1] = r1;
                vh[nj * 2 + 1][0] = r2; vh[nj * 2 + 1][1] = r3;
                ldm_x4(r0, r1, r2, r3, vbl + so);
                vl[nj * 2][0] = r0; vl[nj * 2][1] = r1;
                vl[nj * 2 + 1][0] = r2; vl[nj * 2 + 1][1] = r3;
            }
            #pragma unroll
            for (int nd = 0; nd < 8; nd++) {
                mma16816(o[nd], pah, vh[nd]);
                mma16816(o[nd], pah, vl[nd]);
                mma16816(o[nd], pal, vh[nd]);
            }
        }
        __syncthreads();
    }

    float inv0 = 1.0f / l0, inv1 = 1.0f / l1;
    int gi0 = bi * 128 + w * 16 + grp;
    #pragma unroll
    for (int nd = 0; nd < 8; nd++) {
        int gd = h * HD_ + nd * 8 + tig * 2;
        g_a16[(size_t)gi0 * D_ + gd]           = __float2half_rn(o[nd][0] * inv0);
        g_a16[(size_t)gi0 * D_ + gd + 1]       = __float2half_rn(o[nd][1] * inv0);
        g_a16[(size_t)(gi0 + 8) * D_ + gd]     = __float2half_rn(o[nd][2] * inv1);
        g_a16[(size_t)(gi0 + 8) * D_ + gd + 1] = __float2half_rn(o[nd][3] * inv1);
    }
    #undef FA_LOAD
}

// ---------------- shared GEMM pieces (fp16 single plane) ----------------
template<int BM, int BN>
__device__ __forceinline__ void load_stage16(
    const __half* A, const __half* Bq,
    u32 sbase, int row0, int col0, int K, int k0, int tid)
{
    for (int id = tid; id < BM * 8; id += 256) {
        int r = id >> 3, ck = id & 7;
        u32 so = sw128((u32)(r * 128 + ck * 16));
        cpasync16(sbase + so, A + (size_t)(row0 + r) * K + k0 + ck * 8);
    }
    for (int id = tid; id < BN * 8; id += 256) {
        int r = id >> 3, ck = id & 7;
        u32 so = sw128((u32)(r * 128 + ck * 16));
        cpasync16(sbase + (u32)BM * 128 + so, Bq + (size_t)(col0 + r) * K + k0 + ck * 8);
    }
    asm volatile("cp.async.commit_group;");
}

// EPI: 0 = write g_qkv (fp32), 1 = residual add into g_x, 2 = relu^2 -> g_f16, 3 = Cout
template<int EPI>
__device__ __forceinline__ void epi_store(float v, int gr, int c, float* Cout, int ldc)
{
    if (EPI == 0) {
        g_qkv[(size_t)gr * QKVD_ + c] = v;
    } else if (EPI == 1) {
        g_x[(size_t)gr * D_ + c] += v;
    } else if (EPI == 2) {
        float t = fmaxf(v, 0.f);
        g_f16[(size_t)gr * FF_ + c] = __float2half_rn(t * t);
    } else {
        Cout[(size_t)gr * ldc + c] = v;
    }
}

// ---------------- small GEMM: 128x64, 2-stage, 2 CTAs/SM, fp16 ----------------
template<int EPI, int WSEL, int ASEL>
__global__ __launch_bounds__(256, 2)
void qgemm2_kernel(float* __restrict__ Cout, int layer, int N, int K, int ldc)
{
    constexpr int BM = 128, BN = 64;
    constexpr int MI = 2, NI = 4;
    constexpr u32 STB = (u32)(BM + BN) * 128;

    extern __shared__ char dsm[];
    u32 base = (smem_u32(dsm) + 1023u) & ~1023u;

    int tid = threadIdx.x, lane = tid & 31, wid = tid >> 5;
    int wm = wid % 4, wn = wid / 4;
    int row0 = blockIdx.y * BM, col0 = blockIdx.x * BN;

    const __half* A  = a16sel<ASEL>();
    const __half* Bq = qsel<WSEL>() + (size_t)layer * N * K;
    const float* Sc = scsel<WSEL>() + (size_t)layer * N;

    float acc[MI][NI][4];
    #pragma unroll
    for (int mi = 0; mi < MI; mi++)
        #pragma unroll
        for (int ni = 0; ni < NI; ni++) {
            acc[mi][ni][0] = 0.f; acc[mi][ni][1] = 0.f;
            acc[mi][ni][2] = 0.f; acc[mi][ni][3] = 0.f;
        }

    int n = K >> 6;
    load_stage16<BM, BN>(A, Bq, base,       row0, col0, K, 0,  tid);
    load_stage16<BM, BN>(A, Bq, base + STB, row0, col0, K, 64, tid);

    for (int it = 0; it < n; it++) {
        if (it + 1 < n) { asm volatile("cp.async.wait_group 1;"); }
        else            { asm volatile("cp.async.wait_group 0;"); }
        __syncthreads();

        u32 sb = base + (u32)(it & 1) * STB;
        #pragma unroll
        for (int kc = 0; kc < 4; kc++) {
            u32 ah[MI][4];
            #pragma unroll
            for (int mi = 0; mi < MI; mi++) {
                int lr = wm * 32 + mi * 16 + (lane & 15);
                int ch = kc * 2 + (lane >> 4);
                u32 so = sw128((u32)(lr * 128 + ch * 16));
                ldm_x4(ah[mi][0], ah[mi][1], ah[mi][2], ah[mi][3], sb + so);
            }
            u32 bb[NI][2];
            #pragma unroll
            for (int nj = 0; nj < NI / 2; nj++) {
                int g = lane >> 3;
                int lr = wn * 32 + nj * 16 + (((g >> 1) & 1) << 3) + (lane & 7);
                int ch = kc * 2 + (g & 1);
                u32 r0, r1, r2, r3;
                ldm_x4(r0, r1, r2, r3, sb + (u32)BM * 128 + sw128((u32)(lr * 128 + ch * 16)));
                bb[nj * 2][0] = r0; bb[nj * 2][1] = r1;
                bb[nj * 2 + 1][0] = r2; bb[nj * 2 + 1][1] = r3;
            }
            #pragma unroll
            for (int mi = 0; mi < MI; mi++)
                #pragma unroll
                for (int ni = 0; ni < NI; ni++)
                    mma16816h(acc[mi][ni], ah[mi], bb[ni]);
        }
        __syncthreads();
        if (it + 2 < n)
            load_stage16<BM, BN>(A, Bq, base + (u32)(it & 1) * STB,
                                 row0, col0, K, (it + 2) << 6, tid);
    }

    #pragma unroll
    for (int mi = 0; mi < MI; mi++) {
        #pragma unroll
        for (int ni = 0; ni < NI; ni++) {
            int gr0 = row0 + wm * 32 + mi * 16 + (lane >> 2);
            int gc  = col0 + wn * 32 + ni * 8 + ((lane & 3) << 1);
            #pragma unroll
            for (int half = 0; half < 2; half++) {
                int gr = gr0 + half * 8;
                #pragma unroll
                for (int e = 0; e < 2; e++) {
                    int c = gc + e;
                    if (c >= N) continue;
                    epi_store<EPI>(acc[mi][ni][half * 2 + e] * Sc[c], gr, c, Cout, ldc);
                }
            }
        }
    }
}

// ---------------- big GEMM: 128x128, 2-stage, 2 CTAs/SM, fp16 ----------------
template<int EPI, int WSEL, int ASEL>
__global__ __launch_bounds__(256, 2)
void qgemm3_kernel(float* __restrict__ Cout, int layer, int N, int K, int ldc)
{
    constexpr int BM = 128, BN = 128;
    constexpr int MI = 4, NI = 4;
    constexpr u32 STB = (u32)(BM + BN) * 128;    // 32768

    extern __shared__ char dsm[];
    u32 base = (smem_u32(dsm) + 1023u) & ~1023u;

    int tid = threadIdx.x, lane = tid & 31, wid = tid >> 5;
    int wm = wid % 2, wn = wid / 2;
    int row0 = blockIdx.y * BM, col0 = blockIdx.x * BN;

    const __half* A  = a16sel<ASEL>();
    const __half* Bq = qsel<WSEL>() + (size_t)layer * N * K;
    const float* Sc = scsel<WSEL>() + (size_t)layer * N;

    float acc[MI][NI][4];
    #pragma unroll
    for (int mi = 0; mi < MI; mi++)
        #pragma unroll
        for (int ni = 0; ni < NI; ni++) {
            acc[mi][ni][0] = 0.f; acc[mi][ni][1] = 0.f;
            acc[mi][ni][2] = 0.f; acc[mi][ni][3] = 0.f;
        }

    int n = K >> 6;
    load_stage16<BM, BN>(A, Bq, base,       row0, col0, K, 0,  tid);
    load_stage16<BM, BN>(A, Bq, base + STB, row0, col0, K, 64, tid);

    for (int it = 0; it < n; it++) {
        if (it + 1 < n) { asm volatile("cp.async.wait_group 1;"); }
        else            { asm volatile("cp.async.wait_group 0;"); }
        __syncthreads();

        u32 sb = base + (u32)(it & 1) * STB;
        #pragma unroll
        for (int kc = 0; kc < 4; kc++) {
            u32 ah[MI][4];
            #pragma unroll
            for (int mi = 0; mi < MI; mi++) {
                int lr = wm * 64 + mi * 16 + (lane & 15);
                int ch = kc * 2 + (lane >> 4);
                u32 so = sw128((u32)(lr * 128 + ch * 16));
                ldm_x4(ah[mi][0], ah[mi][1], ah[mi][2], ah[mi][3], sb + so);
            }
            u32 bb[NI][2];
            #pragma unroll
            for (int nj = 0; nj < NI / 2; nj++) {
                int g = lane >> 3;
                int lr = wn * 32 + nj * 16 + (((g >> 1) & 1) << 3) + (lane & 7);
                int ch = kc * 2 + (g & 1);
                u32 r0, r1, r2, r3;
                ldm_x4(r0, r1, r2, r3, sb + (u32)BM * 128 + sw128((u32)(lr * 128 + ch * 16)));
                bb[nj * 2][0] = r0; bb[nj * 2][1] = r1;
                bb[nj * 2 + 1][0] = r2; bb[nj * 2 + 1][1] = r3;
            }
            #pragma unroll
            for (int mi = 0; mi < MI; mi++)
                #pragma unroll
                for (int ni = 0; ni < NI; ni++)
                    mma16816h(acc[mi][ni], ah[mi], bb[ni]);
        }
        __syncthreads();
        if (it + 2 < n)
            load_stage16<BM, BN>(A, Bq, base + (u32)(it & 1) * STB,
                                 row0, col0, K, (it + 2) << 6, tid);
    }

    #pragma unroll
    for (int mi = 0; mi < MI; mi++) {
        #pragma unroll
        for (int ni = 0; ni < NI; ni++) {
            int gr0 = row0 + wm * 64 + mi * 16 + (lane >> 2);
            int gc  = col0 + wn * 32 + ni * 8 + ((lane & 3) << 1);
            #pragma unroll
            for (int half = 0; half < 2; half++) {
                int gr = gr0 + half * 8;
                #pragma unroll
                for (int e = 0; e < 2; e++) {
                    int c = gc + e;
                    if (c >= N) continue;
                    epi_store<EPI>(acc[mi][ni][half * 2 + e] * Sc[c], gr, c, Cout, ldc);
                }
            }
        }
    }
}

#define DSM_SMALL (2 * (128 + 64)  * 128 + 1024)
#define DSM_BIG   (2 * (128 + 128) * 128 + 1024)

// ---------------- host orchestration ----------------
extern "C" void kernel_launch(void* const* d_in, const int* in_sizes, int n_in,
                              void* d_out, int out_size)
{
    (void)in_sizes; (void)n_in; (void)out_size;
    const int*   idx = (const int*)  d_in[0];
    const float* emb = (const float*)d_in[1];
    const float* wq  = (const float*)d_in[2];
    const float* wk  = (const float*)d_in[3];
    const float* wv  = (const float*)d_in[4];
    const float* wo  = (const float*)d_in[5];
    const float* qg  = (const float*)d_in[6];
    const float* wfc = (const float*)d_in[7];
    const float* wpr = (const float*)d_in[8];
    const float* lm  = (const float*)d_in[9];
    float* out = (float*)d_out;

    cudaFuncSetAttribute(qgemm2_kernel<0, 0, 0>,
                         cudaFuncAttributeMaxDynamicSharedMemorySize, DSM_SMALL);
    cudaFuncSetAttribute(qgemm2_kernel<1, 1, 1>,
                         cudaFuncAttributeMaxDynamicSharedMemorySize, DSM_SMALL);
    cudaFuncSetAttribute(qgemm2_kernel<1, 3, 2>,
                         cudaFuncAttributeMaxDynamicSharedMemorySize, DSM_SMALL);
    cudaFuncSetAttribute(qgemm3_kernel<2, 2, 0>,
                         cudaFuncAttributeMaxDynamicSharedMemorySize, DSM_BIG);
    cudaFuncSetAttribute(qgemm3_kernel<3, 4, 0>,
                         cudaFuncAttributeMaxDynamicSharedMemorySize, DSM_BIG);
    cudaFuncSetAttribute(flash_kernel,
                         cudaFuncAttributeMaxDynamicSharedMemorySize, FA_DSM);

    // warp-per-row quant (8 rows of 1024 per block; wpr: 2 rows of 4096)
    quantw_kernel<0, 1><<<L_ * D_ / 8,          256>>>(wq,  L_ * D_,   D_,   QKVD_, 0);
    quantw_kernel<0, 1><<<L_ * KVD_ / 8,        256>>>(wk,  L_ * KVD_, KVD_, QKVD_, 1024);
    quantw_kernel<0, 1><<<L_ * KVD_ / 8,        256>>>(wv,  L_ * KVD_, KVD_, QKVD_, 1280);
    quantw_kernel<1, 1><<<L_ * D_ / 8,          256>>>(wo,  L_ * D_,   L_ * D_,  0, 0);
    quantw_kernel<2, 1><<<L_ * FF_ / 8,         256>>>(wfc, L_ * FF_,  L_ * FF_, 0, 0);
    quantw_kernel<3, 4><<<L_ * D_ / 2,          256>>>(wpr, L_ * D_,   L_ * D_,  0, 0);
    quantw_kernel<4, 1><<<(V_ + 7) / 8,         256>>>(lm,  V_,        V_,       0, 0);

    embed_kernel<<<(S_ * D_) / 256, 256>>>(idx, emb);

    for (int l = 0; l < L_; l++) {
        rmsnorm_h_kernel<<<S_, 256>>>();

        qgemm2_kernel<0, 0, 0><<<dim3(QKVD_ / 64, S_ / 128), 256, DSM_SMALL>>>(
            nullptr, l, QKVD_, D_, QKVD_);

        qkpost_kernel<<<(S_ * 20) / 4, 128>>>(qg + l * H_);
        vtrans_kernel<<<dim3(S_ / 32, KVD_ / 32), dim3(32, 8)>>>();

        flash_kernel<<<dim3(8, H_), 256, FA_DSM>>>();

        qgemm2_kernel<1, 1, 1><<<dim3(D_ / 64, S_ / 128), 256, DSM_SMALL>>>(
            nullptr, l, D_, D_, D_);

        rmsnorm_h_kernel<<<S_, 256>>>();

        qgemm3_kernel<2, 2, 0><<<dim3(FF_ / 128, S_ / 128), 256, DSM_BIG>>>(
            nullptr, l, FF_, D_, FF_);

        qgemm2_kernel<1, 3, 2><<<dim3(D_ / 64, S_ / 128), 256, DSM_SMALL>>>(
            nullptr, l, D_, FF_, D_);
    }

    rmsnorm_h_kernel<<<S_, 256>>>();
    qgemm3_kernel<3, 4, 0><<<dim3(VPAD_ / 128, S_ / 128), 256, DSM_BIG>>>(
        out, 0, V_, D_, V_);
}